// round 3
// baseline (speedup 1.0000x reference)
#include <cuda_runtime.h>
#include <cuda_bf16.h>
#include <cstdint>

// ============ sm_103-safe primitives (NO tcgen05 / 'a'-features) ============
__device__ __forceinline__ uint32_t smem_u32(const void* p) {
    uint32_t a;
    asm("{ .reg .u64 t; cvta.to.shared.u64 t, %1; cvt.u32.u64 %0, t; }" : "=r"(a) : "l"(p));
    return a;
}
__device__ __forceinline__ void ldsm4(uint32_t r[4], uint32_t addr) {
    asm volatile("ldmatrix.sync.aligned.m8n8.x4.shared.b16 {%0,%1,%2,%3}, [%4];"
                 : "=r"(r[0]), "=r"(r[1]), "=r"(r[2]), "=r"(r[3]) : "r"(addr));
}
__device__ __forceinline__ void ldsm4t(uint32_t r[4], uint32_t addr) {
    asm volatile("ldmatrix.sync.aligned.m8n8.x4.trans.shared.b16 {%0,%1,%2,%3}, [%4];"
                 : "=r"(r[0]), "=r"(r[1]), "=r"(r[2]), "=r"(r[3]) : "r"(addr));
}
__device__ __forceinline__ void mma16816(float c[4], const uint32_t a[4],
                                         uint32_t b0, uint32_t b1) {
    asm volatile(
        "mma.sync.aligned.m16n8k16.row.col.f32.bf16.bf16.f32 "
        "{%0,%1,%2,%3},{%4,%5,%6,%7},{%8,%9},{%0,%1,%2,%3};"
        : "+f"(c[0]), "+f"(c[1]), "+f"(c[2]), "+f"(c[3])
        : "r"(a[0]), "r"(a[1]), "r"(a[2]), "r"(a[3]), "r"(b0), "r"(b1));
}
__device__ __forceinline__ uint32_t pack2(__nv_bfloat16 lo, __nv_bfloat16 hi) {
    return ((uint32_t)__bfloat16_as_ushort(hi) << 16) | (uint32_t)__bfloat16_as_ushort(lo);
}
__device__ __forceinline__ void split4(float4 v, uint2& h, uint2& l) {
    __nv_bfloat16 h0 = __float2bfloat16(v.x), h1 = __float2bfloat16(v.y);
    __nv_bfloat16 h2 = __float2bfloat16(v.z), h3 = __float2bfloat16(v.w);
    __nv_bfloat16 l0 = __float2bfloat16(v.x - __bfloat162float(h0));
    __nv_bfloat16 l1 = __float2bfloat16(v.y - __bfloat162float(h1));
    __nv_bfloat16 l2 = __float2bfloat16(v.z - __bfloat162float(h2));
    __nv_bfloat16 l3 = __float2bfloat16(v.w - __bfloat162float(h3));
    h = make_uint2(pack2(h0, h1), pack2(h2, h3));
    l = make_uint2(pack2(l0, l1), pack2(l2, l3));
}
#define SWZ128(o) ((o) ^ (((o) >> 3) & 0x70))
#define SWZ256(o) ((o) ^ (((o) >> 4) & 0x70))

// ============ problem constants ============
#define FIN  1024
#define SEQ  128
#define NKC  16           // 16 chunks of K=64

// ============ SMEM layout (bytes) ============
// chunk buffers (phase 1) union with fp32 scores (phase 2)
#define WT_H   0            // W chunk hi : 128 x 64 bf16, 128B rows
#define WT_L   16384
#define XT_H   32768        // x chunk hi : 64 x 128 bf16, 256B rows
#define XT_L   49152
#define SC_PAD 132          // scores row stride (floats); region [0, 67584)
#define QT_H   68608        // qT hi : 2 heads x [128 s][64 d] bf16 (16KB/head)
#define QT_L   (QT_H + 32768)
#define KT_H   (QT_L + 32768)
#define KT_L   (KT_H + 32768)
#define W_SM   (KT_L + 32768)      // 199680 : 2 x 128 floats
#define BQ_SM  (W_SM + 1024)
#define BK_SM  (BQ_SM + 512)
#define WO_SM  (BK_SM + 512)
#define SMEM_TOTAL (WO_SM + 512)   // 202240

__global__ void __launch_bounds__(512, 1)
Attention_75402445849133_kernel(const float* __restrict__ x,
                                const float* __restrict__ Wq, const float* __restrict__ bq,
                                const float* __restrict__ Wk, const float* __restrict__ bk,
                                const float* __restrict__ Wo, const float* __restrict__ bo,
                                float* __restrict__ out)
{
    extern __shared__ char smem[];
    const uint32_t sbase = smem_u32(smem);
    const int tid = threadIdx.x;
    const int w   = tid >> 5;
    const int lid = tid & 31;
    const int gq  = lid >> 2;
    const int tq  = lid & 3;
    const int g   = blockIdx.x;
    const int b   = blockIdx.y;

    float* scm = (float*)smem;            // phase-2 scores [128][SC_PAD]
    float* wsm = (float*)(smem + W_SM);
    float* bqs = (float*)(smem + BQ_SM);
    float* bks = (float*)(smem + BK_SM);
    float* wos = (float*)(smem + WO_SM);
    if (tid < 128) {
        bqs[tid] = bq[g * 128 + tid];
        bks[tid] = bk[g * 128 + tid];
        wos[tid] = Wo[tid];
    }
    if (tid < 256) wsm[tid] = 0.0f;

    const float* xb = x + (size_t)b * FIN * SEQ;
    const int m0 = (w & 3) * 32;
    const int n0 = (w >> 2) * 32;

    // per-thread load coordinates (W: 16 float4/row; x: 32 float4/row)
    int wrow[4], wf4[4], xrow[4], xf4[4];
    #pragma unroll
    for (int i = 0; i < 4; i++) {
        int idx = i * 512 + tid;
        wrow[i] = idx >> 4;  wf4[i] = idx & 15;
        xrow[i] = idx >> 5;  xf4[i] = idx & 31;
    }

    // ================= Phase 1: projections (p=0 -> Q, p=1 -> K) =================
    #pragma unroll 1
    for (int p = 0; p < 2; p++) {
        const float* Wg = (p ? Wk : Wq) + (size_t)g * 128 * FIN;
        float creg[2][4][4];
        #pragma unroll
        for (int a = 0; a < 2; a++)
            #pragma unroll
            for (int n = 0; n < 4; n++)
                #pragma unroll
                for (int j = 0; j < 4; j++) creg[a][n][j] = 0.f;

        float4 wpre[4], xpre[4];
        #pragma unroll
        for (int i = 0; i < 4; i++) {
            wpre[i] = *(const float4*)(Wg + (size_t)wrow[i] * FIN + wf4[i] * 4);
            xpre[i] = *(const float4*)(xb + (size_t)xrow[i] * SEQ + xf4[i] * 4);
        }

        #pragma unroll 1
        for (int kc = 0; kc < NKC; kc++) {
            // convert + store current chunk
            #pragma unroll
            for (int i = 0; i < 4; i++) {
                uint2 h, l;
                split4(wpre[i], h, l);
                uint32_t off = SWZ128((uint32_t)(wrow[i] * 128 + wf4[i] * 8));
                *(uint2*)(smem + WT_H + off) = h;
                *(uint2*)(smem + WT_L + off) = l;
                split4(xpre[i], h, l);
                off = SWZ256((uint32_t)(xrow[i] * 256 + xf4[i] * 8));
                *(uint2*)(smem + XT_H + off) = h;
                *(uint2*)(smem + XT_L + off) = l;
            }
            __syncthreads();
            // prefetch next chunk (hidden under MMA)
            if (kc < NKC - 1) {
                #pragma unroll
                for (int i = 0; i < 4; i++) {
                    wpre[i] = *(const float4*)(Wg + (size_t)wrow[i] * FIN + (kc + 1) * 64 + wf4[i] * 4);
                    xpre[i] = *(const float4*)(xb + (size_t)((kc + 1) * 64 + xrow[i]) * SEQ + xf4[i] * 4);
                }
            }
            // MMA over this chunk
            #pragma unroll
            for (int ks = 0; ks < 4; ks++) {
                const int k0 = ks * 16;
                uint32_t aH[2][4], aL[2][4];
                #pragma unroll
                for (int mt = 0; mt < 2; mt++) {
                    int row = m0 + mt * 16 + (lid & 15);
                    int col = k0 + ((lid >> 4) << 3);
                    uint32_t off = SWZ128((uint32_t)(row * 128 + col * 2));
                    ldsm4(aH[mt], sbase + WT_H + off);
                    ldsm4(aL[mt], sbase + WT_L + off);
                }
                uint32_t bH[2][4], bL[2][4];
                #pragma unroll
                for (int np = 0; np < 2; np++) {
                    int tL  = lid >> 3;
                    int krw = k0 + ((tL & 1) << 3) + (lid & 7);
                    int nc  = n0 + np * 16 + ((tL >> 1) << 3);
                    uint32_t off = SWZ256((uint32_t)(krw * 256 + nc * 2));
                    ldsm4t(bH[np], sbase + XT_H + off);
                    ldsm4t(bL[np], sbase + XT_L + off);
                }
                #pragma unroll
                for (int mt = 0; mt < 2; mt++)
                    #pragma unroll
                    for (int nt = 0; nt < 4; nt++) {
                        const uint32_t* bh = &bH[nt >> 1][(nt & 1) * 2];
                        const uint32_t* bl = &bL[nt >> 1][(nt & 1) * 2];
                        mma16816(creg[mt][nt], aH[mt], bh[0], bh[1]);
                        mma16816(creg[mt][nt], aH[mt], bl[0], bl[1]);
                        mma16816(creg[mt][nt], aL[mt], bh[0], bh[1]);
                    }
            }
            __syncthreads();
        }
        // writeback: C[ch][s] -> (q|k)T[head][s][d] split bf16 (+bias, q*0.125)
        {
            const int dstH = p ? KT_H : QT_H;
            const int dstL = p ? KT_L : QT_L;
            #pragma unroll
            for (int mt = 0; mt < 2; mt++)
                #pragma unroll
                for (int rj = 0; rj < 2; rj++) {
                    int m = m0 + mt * 16 + rj * 8 + gq;
                    float bias = p ? bks[m] : bqs[m];
                    int head = m >> 6, d = m & 63;
                    char* dh = smem + dstH + head * 16384;
                    char* dl = smem + dstL + head * 16384;
                    #pragma unroll
                    for (int nt = 0; nt < 4; nt++)
                        #pragma unroll
                        for (int jj = 0; jj < 2; jj++) {
                            int n = n0 + nt * 8 + tq * 2 + jj;
                            float v = creg[mt][nt][rj * 2 + jj] + bias;
                            if (!p) v *= 0.125f;
                            __nv_bfloat16 h = __float2bfloat16(v);
                            __nv_bfloat16 l = __float2bfloat16(v - __bfloat162float(h));
                            uint32_t off = SWZ128((uint32_t)(n * 128 + d * 2));
                            *(__nv_bfloat16*)(dh + off) = h;
                            *(__nv_bfloat16*)(dl + off) = l;
                        }
                }
        }
        __syncthreads();
    }

    // ================= Phase 2: per head: scores -> smem, softmax, w reduce ======
    const int s0  = (w & 7) * 16;    // warp's 16 score rows
    const int n0s = (w >> 3) * 64;   // warp's 64 score cols
    #pragma unroll 1
    for (int hd = 0; hd < 2; hd++) {
        const uint32_t qh = sbase + QT_H + hd * 16384;
        const uint32_t ql = sbase + QT_L + hd * 16384;
        const uint32_t kh = sbase + KT_H + hd * 16384;
        const uint32_t kl = sbase + KT_L + hd * 16384;
        float sc[8][4];
        #pragma unroll
        for (int nt = 0; nt < 8; nt++)
            #pragma unroll
            for (int j = 0; j < 4; j++) sc[nt][j] = 0.f;

        #pragma unroll
        for (int ks = 0; ks < 4; ks++) {
            const int k0 = ks * 16;
            uint32_t aH[4], aL[4];
            {
                int row = s0 + (lid & 15);
                int col = k0 + ((lid >> 4) << 3);
                uint32_t off = SWZ128((uint32_t)(row * 128 + col * 2));
                ldsm4(aH, qh + off);
                ldsm4(aL, ql + off);
            }
            #pragma unroll
            for (int np = 0; np < 4; np++) {
                int tL   = lid >> 3;
                int rrow = n0s + np * 16 + ((tL >> 1) << 3) + (lid & 7);
                int ccol = k0 + ((tL & 1) << 3);
                uint32_t off = SWZ128((uint32_t)(rrow * 128 + ccol * 2));
                uint32_t bH[4], bLr[4];
                ldsm4(bH, kh + off);
                ldsm4(bLr, kl + off);
                mma16816(sc[np * 2],     aH, bH[0],  bH[1]);
                mma16816(sc[np * 2],     aH, bLr[0], bLr[1]);
                mma16816(sc[np * 2],     aL, bH[0],  bH[1]);
                mma16816(sc[np * 2 + 1], aH, bH[2],  bH[3]);
                mma16816(sc[np * 2 + 1], aH, bLr[2], bLr[3]);
                mma16816(sc[np * 2 + 1], aL, bH[2],  bH[3]);
            }
        }
        // store scores (fp32) into padded smem
        #pragma unroll
        for (int nt = 0; nt < 8; nt++) {
            int rowA = s0 + gq;
            int col  = n0s + nt * 8 + tq * 2;
            *(float2*)&scm[rowA * SC_PAD + col]       = make_float2(sc[nt][0], sc[nt][1]);
            *(float2*)&scm[(rowA + 8) * SC_PAD + col] = make_float2(sc[nt][2], sc[nt][3]);
        }
        __syncthreads();
        // softmax + scale by Wo[row]/Z (4 threads per row, bank-rotated)
        {
            const int row = tid >> 2, sub = tid & 3;
            float e[32];
            float mx = -1e30f;
            #pragma unroll
            for (int i = 0; i < 32; i++) {
                int col = sub * 32 + ((i + 8 * sub) & 31);
                e[i] = scm[row * SC_PAD + col];
                mx = fmaxf(mx, e[i]);
            }
            mx = fmaxf(mx, __shfl_xor_sync(0xffffffffu, mx, 1));
            mx = fmaxf(mx, __shfl_xor_sync(0xffffffffu, mx, 2));
            float Z = 0.f;
            #pragma unroll
            for (int i = 0; i < 32; i++) { e[i] = __expf(e[i] - mx); Z += e[i]; }
            Z += __shfl_xor_sync(0xffffffffu, Z, 1);
            Z += __shfl_xor_sync(0xffffffffu, Z, 2);
            const float cf = wos[row] / Z;
            #pragma unroll
            for (int i = 0; i < 32; i++) {
                int col = sub * 32 + ((i + 8 * sub) & 31);
                scm[row * SC_PAD + col] = e[i] * cf;
            }
        }
        __syncthreads();
        // w[t] = sum_s scaled_attn[s][t]
        {
            const int t = tid & 127, sblk = tid >> 7;
            float s = 0.f;
            #pragma unroll 8
            for (int j = 0; j < 32; j++) s += scm[(sblk * 32 + j) * SC_PAD + t];
            atomicAdd(&wsm[hd * 128 + t], s);
        }
        __syncthreads();
    }

    // ================= Phase 3: out[b, g*128+f] = sum_t w[head][t] * x[b,f,t] + bo
    if (tid < 128) {
        const float* wv = wsm + (tid >> 6) * 128;
        const float4* x4 = (const float4*)(xb + (size_t)(g * 128 + tid) * SEQ);
        float acc = 0.f;
        #pragma unroll 8
        for (int t4 = 0; t4 < 32; t4++) {
            float4 xv = x4[t4];
            acc += xv.x * wv[t4 * 4 + 0] + xv.y * wv[t4 * 4 + 1]
                 + xv.z * wv[t4 * 4 + 2] + xv.w * wv[t4 * 4 + 3];
        }
        out[(size_t)b * FIN + g * 128 + tid] = acc + bo[0];
    }
}

extern "C" void kernel_launch(void* const* d_in, const int* in_sizes, int n_in,
                              void* d_out, int out_size)
{
    (void)in_sizes; (void)n_in; (void)out_size;
    const float* x  = (const float*)d_in[0];
    const float* Wq = (const float*)d_in[1];
    const float* bq = (const float*)d_in[2];
    const float* Wk = (const float*)d_in[3];
    const float* bk = (const float*)d_in[4];
    const float* Wo = (const float*)d_in[5];
    const float* bo = (const float*)d_in[6];
    float* out = (float*)d_out;

    cudaFuncSetAttribute(Attention_75402445849133_kernel,
                         cudaFuncAttributeMaxDynamicSharedMemorySize, SMEM_TOTAL);
    dim3 grid(8, 256, 1);
    Attention_75402445849133_kernel<<<grid, 512, SMEM_TOTAL>>>(x, Wq, bq, Wk, bk, Wo, bo, out);
}

// round 4
// speedup vs baseline: 1.1537x; 1.1537x over previous
#include <cuda_runtime.h>
#include <cuda_bf16.h>
#include <cstdint>

// ============ sm_103-safe primitives (NO tcgen05 / 'a'-features) ============
__device__ __forceinline__ uint32_t smem_u32(const void* p) {
    uint32_t a;
    asm("{ .reg .u64 t; cvta.to.shared.u64 t, %1; cvt.u32.u64 %0, t; }" : "=r"(a) : "l"(p));
    return a;
}
__device__ __forceinline__ void ldsm4(uint32_t r[4], uint32_t addr) {
    asm volatile("ldmatrix.sync.aligned.m8n8.x4.shared.b16 {%0,%1,%2,%3}, [%4];"
                 : "=r"(r[0]), "=r"(r[1]), "=r"(r[2]), "=r"(r[3]) : "r"(addr));
}
__device__ __forceinline__ void ldsm4t(uint32_t r[4], uint32_t addr) {
    asm volatile("ldmatrix.sync.aligned.m8n8.x4.trans.shared.b16 {%0,%1,%2,%3}, [%4];"
                 : "=r"(r[0]), "=r"(r[1]), "=r"(r[2]), "=r"(r[3]) : "r"(addr));
}
__device__ __forceinline__ void mma16816(float c[4], const uint32_t a[4],
                                         uint32_t b0, uint32_t b1) {
    asm volatile(
        "mma.sync.aligned.m16n8k16.row.col.f32.bf16.bf16.f32 "
        "{%0,%1,%2,%3},{%4,%5,%6,%7},{%8,%9},{%0,%1,%2,%3};"
        : "+f"(c[0]), "+f"(c[1]), "+f"(c[2]), "+f"(c[3])
        : "r"(a[0]), "r"(a[1]), "r"(a[2]), "r"(a[3]), "r"(b0), "r"(b1));
}
__device__ __forceinline__ uint32_t pack2(__nv_bfloat16 lo, __nv_bfloat16 hi) {
    return ((uint32_t)__bfloat16_as_ushort(hi) << 16) | (uint32_t)__bfloat16_as_ushort(lo);
}
__device__ __forceinline__ void split4(float4 v, uint2& h, uint2& l) {
    __nv_bfloat16 h0 = __float2bfloat16(v.x), h1 = __float2bfloat16(v.y);
    __nv_bfloat16 h2 = __float2bfloat16(v.z), h3 = __float2bfloat16(v.w);
    __nv_bfloat16 l0 = __float2bfloat16(v.x - __bfloat162float(h0));
    __nv_bfloat16 l1 = __float2bfloat16(v.y - __bfloat162float(h1));
    __nv_bfloat16 l2 = __float2bfloat16(v.z - __bfloat162float(h2));
    __nv_bfloat16 l3 = __float2bfloat16(v.w - __bfloat162float(h3));
    h = make_uint2(pack2(h0, h1), pack2(h2, h3));
    l = make_uint2(pack2(l0, l1), pack2(l2, l3));
}
#define SWZ64(o)  ((o) ^ (((o) >> 2) & 0x30))
#define SWZ128(o) ((o) ^ (((o) >> 3) & 0x70))
#define SWZ256(o) ((o) ^ (((o) >> 4) & 0x70))

// ============ problem constants ============
#define FIN  1024
#define SEQ  128
#define CH   32            // K per chunk
#define NC   32            // chunks per projection

// ============ SMEM layout (bytes) ============
// double-buffered chunk: [W_H 8K | W_L 8K | X_H 8K | X_L 8K] x 2
#define BUF_SZ  32768
#define BW_H    0
#define BW_L    8192
#define BX_H    16384
#define BX_L    24576
#define QT_H    65536          // 2 heads x [128 s][64 d] bf16 hi
#define QT_L    98304
#define KT_H    131072
#define KT_L    163840
#define W_SM    196608         // 2 x 128 floats
#define BQ_SM   197632
#define BK_SM   198144
#define WO_SM   198656
#define SMEM_TOTAL 199168

__global__ void __launch_bounds__(384, 1)
Attention_75402445849133_kernel(const float* __restrict__ x,
                                const float* __restrict__ Wq, const float* __restrict__ bq,
                                const float* __restrict__ Wk, const float* __restrict__ bk,
                                const float* __restrict__ Wo, const float* __restrict__ bo,
                                float* __restrict__ out)
{
    extern __shared__ char smem[];
    const uint32_t sbase = smem_u32(smem);
    const int tid = threadIdx.x;
    const int w   = tid >> 5;      // 0-7 consumers, 8-11 producers
    const int lid = tid & 31;
    const int gq  = lid >> 2;
    const int tq  = lid & 3;
    const int g   = blockIdx.x;
    const int b   = blockIdx.y;

    float* wsm = (float*)(smem + W_SM);
    float* bqs = (float*)(smem + BQ_SM);
    float* bks = (float*)(smem + BK_SM);
    float* wos = (float*)(smem + WO_SM);
    if (tid < 128) {
        bqs[tid] = bq[g * 128 + tid];
        bks[tid] = bk[g * 128 + tid];
        wos[tid] = Wo[tid];
    }
    if (tid >= 128 && tid < 384) wsm[tid - 128] = 0.0f;

    const float* xb = x + (size_t)b * FIN * SEQ;
    const int m0 = (w & 3) * 32;     // consumer channel-row tile
    const int n0 = (w >> 2) * 64;    // consumer s-column tile
    const int tp = tid - 256;        // producer lane 0..127

    // ================= Phase 1: projections (p=0 -> Q, p=1 -> K) =================
    #pragma unroll 1
    for (int p = 0; p < 2; p++) {
        const float* Wg = (p ? Wk : Wq) + (size_t)g * 128 * FIN;

        float creg[2][8][4];
        float4 wv[8], xv[8];

        if (w < 8) {
            #pragma unroll
            for (int a = 0; a < 2; a++)
                #pragma unroll
                for (int n = 0; n < 8; n++)
                    #pragma unroll
                    for (int j = 0; j < 4; j++) creg[a][n][j] = 0.f;
        } else {
            // prologue: chunk 0 -> buf0, prefetch chunk 1 into regs
            #pragma unroll
            for (int j = 0; j < 8; j++) {
                int idx = j * 128 + tp;
                wv[j] = *(const float4*)(Wg + (size_t)(idx >> 3) * FIN + (idx & 7) * 4);
                xv[j] = *(const float4*)(xb + (size_t)(idx >> 5) * SEQ + (idx & 31) * 4);
            }
            #pragma unroll
            for (int j = 0; j < 8; j++) {
                int idx = j * 128 + tp;
                uint2 h, l;
                split4(wv[j], h, l);
                uint32_t off = SWZ64((uint32_t)((idx >> 3) * 64 + (idx & 7) * 8));
                *(uint2*)(smem + BW_H + off) = h;
                *(uint2*)(smem + BW_L + off) = l;
                split4(xv[j], h, l);
                off = SWZ256((uint32_t)((idx >> 5) * 256 + (idx & 31) * 8));
                *(uint2*)(smem + BX_H + off) = h;
                *(uint2*)(smem + BX_L + off) = l;
            }
            #pragma unroll
            for (int j = 0; j < 8; j++) {
                int idx = j * 128 + tp;
                wv[j] = *(const float4*)(Wg + (size_t)(idx >> 3) * FIN + CH + (idx & 7) * 4);
                xv[j] = *(const float4*)(xb + (size_t)(CH + (idx >> 5)) * SEQ + (idx & 31) * 4);
            }
        }
        __syncthreads();

        #pragma unroll 1
        for (int kc = 0; kc < NC; kc++) {
            if (w < 8) {
                const uint32_t bufb = sbase + (kc & 1) * BUF_SZ;
                #pragma unroll
                for (int ks = 0; ks < 2; ks++) {
                    const int k0 = ks * 16;
                    uint32_t aH[2][4], aL[2][4];
                    #pragma unroll
                    for (int mt = 0; mt < 2; mt++) {
                        int row = m0 + mt * 16 + (lid & 15);
                        int col = k0 + ((lid >> 4) << 3);
                        uint32_t off = SWZ64((uint32_t)(row * 64 + col * 2));
                        ldsm4(aH[mt], bufb + BW_H + off);
                        ldsm4(aL[mt], bufb + BW_L + off);
                    }
                    #pragma unroll
                    for (int np = 0; np < 4; np++) {
                        int tL  = lid >> 3;
                        int krw = k0 + ((tL & 1) << 3) + (lid & 7);
                        int nc  = n0 + np * 16 + ((tL >> 1) << 3);
                        uint32_t off = SWZ256((uint32_t)(krw * 256 + nc * 2));
                        uint32_t bH[4], bL[4];
                        ldsm4t(bH, bufb + BX_H + off);
                        ldsm4t(bL, bufb + BX_L + off);
                        #pragma unroll
                        for (int mt = 0; mt < 2; mt++) {
                            mma16816(creg[mt][np * 2],     aH[mt], bH[0], bH[1]);
                            mma16816(creg[mt][np * 2],     aH[mt], bL[0], bL[1]);
                            mma16816(creg[mt][np * 2],     aL[mt], bH[0], bH[1]);
                            mma16816(creg[mt][np * 2 + 1], aH[mt], bH[2], bH[3]);
                            mma16816(creg[mt][np * 2 + 1], aH[mt], bL[2], bL[3]);
                            mma16816(creg[mt][np * 2 + 1], aL[mt], bH[2], bH[3]);
                        }
                    }
                }
            } else {
                if (kc < NC - 1) {
                    char* bufb = smem + ((kc + 1) & 1) * BUF_SZ;
                    #pragma unroll
                    for (int j = 0; j < 8; j++) {
                        int idx = j * 128 + tp;
                        uint2 h, l;
                        split4(wv[j], h, l);
                        uint32_t off = SWZ64((uint32_t)((idx >> 3) * 64 + (idx & 7) * 8));
                        *(uint2*)(bufb + BW_H + off) = h;
                        *(uint2*)(bufb + BW_L + off) = l;
                        split4(xv[j], h, l);
                        off = SWZ256((uint32_t)((idx >> 5) * 256 + (idx & 31) * 8));
                        *(uint2*)(bufb + BX_H + off) = h;
                        *(uint2*)(bufb + BX_L + off) = l;
                    }
                }
                if (kc < NC - 2) {
                    const int kn = (kc + 2) * CH;
                    #pragma unroll
                    for (int j = 0; j < 8; j++) {
                        int idx = j * 128 + tp;
                        wv[j] = *(const float4*)(Wg + (size_t)(idx >> 3) * FIN + kn + (idx & 7) * 4);
                        xv[j] = *(const float4*)(xb + (size_t)(kn + (idx >> 5)) * SEQ + (idx & 31) * 4);
                    }
                }
            }
            __syncthreads();
        }

        // writeback: C[ch][s] -> (q|k)T[head][s][d] split bf16 (+bias, q*0.125)
        if (w < 8) {
            const int dstH = p ? KT_H : QT_H;
            const int dstL = p ? KT_L : QT_L;
            #pragma unroll
            for (int mt = 0; mt < 2; mt++)
                #pragma unroll
                for (int rj = 0; rj < 2; rj++) {
                    int m = m0 + mt * 16 + rj * 8 + gq;
                    float bias = p ? bks[m] : bqs[m];
                    int head = m >> 6, d = m & 63;
                    char* dh = smem + dstH + head * 16384;
                    char* dl = smem + dstL + head * 16384;
                    #pragma unroll
                    for (int nt = 0; nt < 8; nt++)
                        #pragma unroll
                        for (int jj = 0; jj < 2; jj++) {
                            int n = n0 + nt * 8 + tq * 2 + jj;
                            float v = creg[mt][nt][rj * 2 + jj] + bias;
                            if (!p) v *= 0.125f;
                            __nv_bfloat16 h = __float2bfloat16(v);
                            __nv_bfloat16 l = __float2bfloat16(v - __bfloat162float(h));
                            uint32_t off = SWZ128((uint32_t)(n * 128 + d * 2));
                            *(__nv_bfloat16*)(dh + off) = h;
                            *(__nv_bfloat16*)(dl + off) = l;
                        }
                }
        }
    }
    __syncthreads();

    // ================= Phase 2: scores + softmax + w reduction (8 consumer warps)
    if (w < 8) {
        const int head = w >> 2;
        const int sb0  = (w & 3) * 32;
        const uint32_t qh = sbase + QT_H + head * 16384;
        const uint32_t ql = sbase + QT_L + head * 16384;
        const uint32_t kh = sbase + KT_H + head * 16384;
        const uint32_t kl = sbase + KT_L + head * 16384;

        float wacc[16][2];
        #pragma unroll
        for (int nt = 0; nt < 16; nt++) { wacc[nt][0] = 0.f; wacc[nt][1] = 0.f; }

        #pragma unroll 1
        for (int chunk = 0; chunk < 2; chunk++) {
            const int s0 = sb0 + chunk * 16;
            float sc[16][4];
            #pragma unroll
            for (int nt = 0; nt < 16; nt++)
                #pragma unroll
                for (int j = 0; j < 4; j++) sc[nt][j] = 0.f;

            #pragma unroll
            for (int ks = 0; ks < 4; ks++) {
                const int k0 = ks * 16;
                uint32_t aH[4], aL[4];
                {
                    int row = s0 + (lid & 15);
                    int col = k0 + ((lid >> 4) << 3);
                    uint32_t off = SWZ128((uint32_t)(row * 128 + col * 2));
                    ldsm4(aH, qh + off);
                    ldsm4(aL, ql + off);
                }
                #pragma unroll
                for (int np = 0; np < 8; np++) {
                    int tL   = lid >> 3;
                    int rrow = np * 16 + ((tL >> 1) << 3) + (lid & 7);
                    int ccol = k0 + ((tL & 1) << 3);
                    uint32_t off = SWZ128((uint32_t)(rrow * 128 + ccol * 2));
                    uint32_t bH[4], bLr[4];
                    ldsm4(bH, kh + off);
                    ldsm4(bLr, kl + off);
                    mma16816(sc[np * 2],     aH, bH[0],  bH[1]);
                    mma16816(sc[np * 2],     aH, bLr[0], bLr[1]);
                    mma16816(sc[np * 2],     aL, bH[0],  bH[1]);
                    mma16816(sc[np * 2 + 1], aH, bH[2],  bH[3]);
                    mma16816(sc[np * 2 + 1], aH, bLr[2], bLr[3]);
                    mma16816(sc[np * 2 + 1], aL, bH[2],  bH[3]);
                }
            }
            float mx0 = -1e30f, mx1 = -1e30f;
            #pragma unroll
            for (int nt = 0; nt < 16; nt++) {
                mx0 = fmaxf(mx0, fmaxf(sc[nt][0], sc[nt][1]));
                mx1 = fmaxf(mx1, fmaxf(sc[nt][2], sc[nt][3]));
            }
            mx0 = fmaxf(mx0, __shfl_xor_sync(0xffffffffu, mx0, 1));
            mx0 = fmaxf(mx0, __shfl_xor_sync(0xffffffffu, mx0, 2));
            mx1 = fmaxf(mx1, __shfl_xor_sync(0xffffffffu, mx1, 1));
            mx1 = fmaxf(mx1, __shfl_xor_sync(0xffffffffu, mx1, 2));
            float Z0 = 0.f, Z1 = 0.f;
            #pragma unroll
            for (int nt = 0; nt < 16; nt++) {
                sc[nt][0] = __expf(sc[nt][0] - mx0); Z0 += sc[nt][0];
                sc[nt][1] = __expf(sc[nt][1] - mx0); Z0 += sc[nt][1];
                sc[nt][2] = __expf(sc[nt][2] - mx1); Z1 += sc[nt][2];
                sc[nt][3] = __expf(sc[nt][3] - mx1); Z1 += sc[nt][3];
            }
            Z0 += __shfl_xor_sync(0xffffffffu, Z0, 1);
            Z0 += __shfl_xor_sync(0xffffffffu, Z0, 2);
            Z1 += __shfl_xor_sync(0xffffffffu, Z1, 1);
            Z1 += __shfl_xor_sync(0xffffffffu, Z1, 2);
            const float c0 = wos[s0 + gq]     / Z0;
            const float c1 = wos[s0 + 8 + gq] / Z1;
            #pragma unroll
            for (int nt = 0; nt < 16; nt++) {
                wacc[nt][0] += sc[nt][0] * c0 + sc[nt][2] * c1;
                wacc[nt][1] += sc[nt][1] * c0 + sc[nt][3] * c1;
            }
        }
        #pragma unroll
        for (int d = 4; d < 32; d <<= 1)
            #pragma unroll
            for (int nt = 0; nt < 16; nt++) {
                wacc[nt][0] += __shfl_xor_sync(0xffffffffu, wacc[nt][0], d);
                wacc[nt][1] += __shfl_xor_sync(0xffffffffu, wacc[nt][1], d);
            }
        if (lid < 4) {
            #pragma unroll
            for (int nt = 0; nt < 16; nt++) {
                atomicAdd(&wsm[head * 128 + nt * 8 + 2 * lid],     wacc[nt][0]);
                atomicAdd(&wsm[head * 128 + nt * 8 + 2 * lid + 1], wacc[nt][1]);
            }
        }
    }
    __syncthreads();

    // ================= Phase 3: out[b, g*128+f] = sum_t w[head][t] * x[b,f,t] + bo
    if (tid < 128) {
        const float* wv2 = wsm + (tid >> 6) * 128;
        const float4* x4 = (const float4*)(xb + (size_t)(g * 128 + tid) * SEQ);
        float acc = 0.f;
        #pragma unroll 8
        for (int t4 = 0; t4 < 32; t4++) {
            float4 xvv = x4[t4];
            acc += xvv.x * wv2[t4 * 4 + 0] + xvv.y * wv2[t4 * 4 + 1]
                 + xvv.z * wv2[t4 * 4 + 2] + xvv.w * wv2[t4 * 4 + 3];
        }
        out[(size_t)b * FIN + g * 128 + tid] = acc + bo[0];
    }
}

extern "C" void kernel_launch(void* const* d_in, const int* in_sizes, int n_in,
                              void* d_out, int out_size)
{
    (void)in_sizes; (void)n_in; (void)out_size;
    const float* x  = (const float*)d_in[0];
    const float* Wq = (const float*)d_in[1];
    const float* bq = (const float*)d_in[2];
    const float* Wk = (const float*)d_in[3];
    const float* bk = (const float*)d_in[4];
    const float* Wo = (const float*)d_in[5];
    const float* bo = (const float*)d_in[6];
    float* out = (float*)d_out;

    cudaFuncSetAttribute(Attention_75402445849133_kernel,
                         cudaFuncAttributeMaxDynamicSharedMemorySize, SMEM_TOTAL);
    dim3 grid(8, 256, 1);
    Attention_75402445849133_kernel<<<grid, 384, SMEM_TOTAL>>>(x, Wq, bq, Wk, bk, Wo, bo, out);
}

// round 5
// speedup vs baseline: 1.3316x; 1.1542x over previous
#include <cuda_runtime.h>
#include <cuda_bf16.h>
#include <cstdint>

// ============ sm_103-safe primitives ============
__device__ __forceinline__ uint32_t smem_u32(const void* p) {
    uint32_t a;
    asm("{ .reg .u64 t; cvta.to.shared.u64 t, %1; cvt.u32.u64 %0, t; }" : "=r"(a) : "l"(p));
    return a;
}
__device__ __forceinline__ void ldsm4(uint32_t r[4], uint32_t addr) {
    asm volatile("ldmatrix.sync.aligned.m8n8.x4.shared.b16 {%0,%1,%2,%3}, [%4];"
                 : "=r"(r[0]), "=r"(r[1]), "=r"(r[2]), "=r"(r[3]) : "r"(addr));
}
__device__ __forceinline__ void ldsm4t(uint32_t r[4], uint32_t addr) {
    asm volatile("ldmatrix.sync.aligned.m8n8.x4.trans.shared.b16 {%0,%1,%2,%3}, [%4];"
                 : "=r"(r[0]), "=r"(r[1]), "=r"(r[2]), "=r"(r[3]) : "r"(addr));
}
__device__ __forceinline__ void mma16816(float c[4], const uint32_t a[4],
                                         uint32_t b0, uint32_t b1) {
    asm volatile(
        "mma.sync.aligned.m16n8k16.row.col.f32.bf16.bf16.f32 "
        "{%0,%1,%2,%3},{%4,%5,%6,%7},{%8,%9},{%0,%1,%2,%3};"
        : "+f"(c[0]), "+f"(c[1]), "+f"(c[2]), "+f"(c[3])
        : "r"(a[0]), "r"(a[1]), "r"(a[2]), "r"(a[3]), "r"(b0), "r"(b1));
}
__device__ __forceinline__ uint32_t pack2(__nv_bfloat16 lo, __nv_bfloat16 hi) {
    return ((uint32_t)__bfloat16_as_ushort(hi) << 16) | (uint32_t)__bfloat16_as_ushort(lo);
}
__device__ __forceinline__ void split4(float4 v, uint2& h, uint2& l) {
    __nv_bfloat16 h0 = __float2bfloat16(v.x), h1 = __float2bfloat16(v.y);
    __nv_bfloat16 h2 = __float2bfloat16(v.z), h3 = __float2bfloat16(v.w);
    __nv_bfloat16 l0 = __float2bfloat16(v.x - __bfloat162float(h0));
    __nv_bfloat16 l1 = __float2bfloat16(v.y - __bfloat162float(h1));
    __nv_bfloat16 l2 = __float2bfloat16(v.z - __bfloat162float(h2));
    __nv_bfloat16 l3 = __float2bfloat16(v.w - __bfloat162float(h3));
    h = make_uint2(pack2(h0, h1), pack2(h2, h3));
    l = make_uint2(pack2(l0, l1), pack2(l2, l3));
}
__device__ __forceinline__ void cpa16(uint32_t dst, const void* src) {
    asm volatile("cp.async.cg.shared.global [%0], [%1], 16;" :: "r"(dst), "l"(src) : "memory");
}
#define CP_COMMIT() asm volatile("cp.async.commit_group;" ::: "memory")
#define CP_WAIT1()  asm volatile("cp.async.wait_group 1;" ::: "memory")
#define CP_WAIT0()  asm volatile("cp.async.wait_group 0;" ::: "memory")
#define SWZ64(o)  ((o) ^ (((o) >> 2) & 0x30))
#define SWZ128(o) ((o) ^ (((o) >> 3) & 0x70))
#define SWZ256(o) ((o) ^ (((o) >> 4) & 0x70))

// ============ problem constants ============
#define FIN  1024
#define SEQ  128
#define CH   32            // K per chunk
#define NC   32            // chunks per projection

// ============ pre-split global staging (bf16 hi/lo) ============
__device__ __align__(16) __nv_bfloat16 g_WqH[1024 * 1024];
__device__ __align__(16) __nv_bfloat16 g_WqL[1024 * 1024];
__device__ __align__(16) __nv_bfloat16 g_WkH[1024 * 1024];
__device__ __align__(16) __nv_bfloat16 g_WkL[1024 * 1024];
__device__ __align__(16) __nv_bfloat16 g_xH[256 * 1024 * 128];
__device__ __align__(16) __nv_bfloat16 g_xL[256 * 1024 * 128];

__global__ void __launch_bounds__(256) prep_w_kernel(const float* __restrict__ Wq,
                                                     const float* __restrict__ Wk) {
    int i = blockIdx.x * 256 + threadIdx.x;         // 262144 threads, 4 floats each
    float4 v = ((const float4*)Wq)[i];
    uint2 h, l;
    split4(v, h, l);
    ((uint2*)g_WqH)[i] = h; ((uint2*)g_WqL)[i] = l;
    v = ((const float4*)Wk)[i];
    split4(v, h, l);
    ((uint2*)g_WkH)[i] = h; ((uint2*)g_WkL)[i] = l;
}
__global__ void __launch_bounds__(256) prep_x_kernel(const float* __restrict__ x) {
    size_t i = (size_t)blockIdx.x * 256 + threadIdx.x;  // 8388608 threads
    float4 v = ((const float4*)x)[i];
    uint2 h, l;
    split4(v, h, l);
    ((uint2*)g_xH)[i] = h; ((uint2*)g_xL)[i] = l;
}

// ============ SMEM layout (bytes) ============
#define BUF_SZ  32768
#define BW_H    0
#define BW_L    8192
#define BX_H    16384
#define BX_L    24576
#define QT_H    65536          // 2 heads x [128 s][64 d] bf16 hi
#define QT_L    98304
#define KT_H    131072
#define KT_L    163840
#define W_SM    196608         // 2 x 128 floats
#define BQ_SM   197632
#define BK_SM   198144
#define WO_SM   198656
#define SMEM_TOTAL 199168

__global__ void __launch_bounds__(256, 1)
Attention_75402445849133_kernel(const float* __restrict__ x,
                                const float* __restrict__ bq, const float* __restrict__ bk,
                                const float* __restrict__ Wo, const float* __restrict__ bo,
                                float* __restrict__ out)
{
    extern __shared__ char smem[];
    const uint32_t sbase = smem_u32(smem);
    const int tid = threadIdx.x;
    const int w   = tid >> 5;
    const int lid = tid & 31;
    const int gq  = lid >> 2;
    const int tq  = lid & 3;
    const int g   = blockIdx.x;
    const int b   = blockIdx.y;

    float* wsm = (float*)(smem + W_SM);
    float* bqs = (float*)(smem + BQ_SM);
    float* bks = (float*)(smem + BK_SM);
    float* wos = (float*)(smem + WO_SM);
    if (tid < 128) {
        bqs[tid] = bq[g * 128 + tid];
        bks[tid] = bk[g * 128 + tid];
        wos[tid] = Wo[tid];
    }
    wsm[tid] = 0.0f;

    const float* xb = x + (size_t)b * FIN * SEQ;
    const __nv_bfloat16* xbH = g_xH + (size_t)b * FIN * SEQ;
    const __nv_bfloat16* xbL = g_xL + (size_t)b * FIN * SEQ;
    const int m0 = (w & 3) * 32;
    const int n0 = (w >> 2) * 64;

    // precompute per-thread cp.async coordinates
    // W granules: 512 (8KB): row=idx>>2 (0..127), gc=idx&3; x granules: 512: xr=idx>>4, xg=idx&15
    int wr[2], wg[2], xr[2], xg[2];
    uint32_t woff[2], xoff[2];
    #pragma unroll
    for (int j = 0; j < 2; j++) {
        int idx = j * 256 + tid;
        wr[j] = idx >> 2;  wg[j] = idx & 3;
        xr[j] = idx >> 4;  xg[j] = idx & 15;
        woff[j] = SWZ64((uint32_t)(wr[j] * 64 + wg[j] * 16));
        xoff[j] = SWZ256((uint32_t)(xr[j] * 256 + xg[j] * 16));
    }

    // ================= Phase 1: projections (p=0 -> Q, p=1 -> K) =================
    #pragma unroll 1
    for (int p = 0; p < 2; p++) {
        const __nv_bfloat16* WH = (p ? g_WkH : g_WqH) + (size_t)g * 128 * FIN;
        const __nv_bfloat16* WL = (p ? g_WkL : g_WqL) + (size_t)g * 128 * FIN;

        float creg[2][8][4];
        #pragma unroll
        for (int a = 0; a < 2; a++)
            #pragma unroll
            for (int n = 0; n < 8; n++)
                #pragma unroll
                for (int j = 0; j < 4; j++) creg[a][n][j] = 0.f;

        // prologue: issue chunk 0
        #pragma unroll
        for (int j = 0; j < 2; j++) {
            cpa16(sbase + BW_H + woff[j], WH + wr[j] * FIN + wg[j] * 8);
            cpa16(sbase + BW_L + woff[j], WL + wr[j] * FIN + wg[j] * 8);
            cpa16(sbase + BX_H + xoff[j], xbH + xr[j] * SEQ + xg[j] * 8);
            cpa16(sbase + BX_L + xoff[j], xbL + xr[j] * SEQ + xg[j] * 8);
        }
        CP_COMMIT();

        #pragma unroll 1
        for (int kc = 0; kc < NC; kc++) {
            if (kc + 1 < NC) {
                const uint32_t nb = sbase + ((kc + 1) & 1) * BUF_SZ;
                const int kn = (kc + 1) * CH;
                #pragma unroll
                for (int j = 0; j < 2; j++) {
                    cpa16(nb + BW_H + woff[j], WH + wr[j] * FIN + kn + wg[j] * 8);
                    cpa16(nb + BW_L + woff[j], WL + wr[j] * FIN + kn + wg[j] * 8);
                    cpa16(nb + BX_H + xoff[j], xbH + (size_t)(kn + xr[j]) * SEQ + xg[j] * 8);
                    cpa16(nb + BX_L + xoff[j], xbL + (size_t)(kn + xr[j]) * SEQ + xg[j] * 8);
                }
                CP_COMMIT();
                CP_WAIT1();
            } else {
                CP_WAIT0();
            }
            __syncthreads();

            const uint32_t bufb = sbase + (kc & 1) * BUF_SZ;
            #pragma unroll
            for (int ks = 0; ks < 2; ks++) {
                const int k0 = ks * 16;
                uint32_t aH[2][4], aL[2][4];
                #pragma unroll
                for (int mt = 0; mt < 2; mt++) {
                    int row = m0 + mt * 16 + (lid & 15);
                    int col = k0 + ((lid >> 4) << 3);
                    uint32_t off = SWZ64((uint32_t)(row * 64 + col * 2));
                    ldsm4(aH[mt], bufb + BW_H + off);
                    ldsm4(aL[mt], bufb + BW_L + off);
                }
                #pragma unroll
                for (int np = 0; np < 4; np++) {
                    int tL  = lid >> 3;
                    int krw = k0 + ((tL & 1) << 3) + (lid & 7);
                    int nc  = n0 + np * 16 + ((tL >> 1) << 3);
                    uint32_t off = SWZ256((uint32_t)(krw * 256 + nc * 2));
                    uint32_t bH[4], bL[4];
                    ldsm4t(bH, bufb + BX_H + off);
                    ldsm4t(bL, bufb + BX_L + off);
                    #pragma unroll
                    for (int mt = 0; mt < 2; mt++) {
                        mma16816(creg[mt][np * 2],     aH[mt], bH[0], bH[1]);
                        mma16816(creg[mt][np * 2],     aH[mt], bL[0], bL[1]);
                        mma16816(creg[mt][np * 2],     aL[mt], bH[0], bH[1]);
                        mma16816(creg[mt][np * 2 + 1], aH[mt], bH[2], bH[3]);
                        mma16816(creg[mt][np * 2 + 1], aH[mt], bL[2], bL[3]);
                        mma16816(creg[mt][np * 2 + 1], aL[mt], bH[2], bH[3]);
                    }
                }
            }
            __syncthreads();
        }

        // writeback: C[ch][s] -> (q|k)T[head][s][d] split bf16 (+bias, q*0.125)
        {
            const int dstH = p ? KT_H : QT_H;
            const int dstL = p ? KT_L : QT_L;
            #pragma unroll
            for (int mt = 0; mt < 2; mt++)
                #pragma unroll
                for (int rj = 0; rj < 2; rj++) {
                    int m = m0 + mt * 16 + rj * 8 + gq;
                    float bias = p ? bks[m] : bqs[m];
                    int head = m >> 6, d = m & 63;
                    char* dh = smem + dstH + head * 16384;
                    char* dl = smem + dstL + head * 16384;
                    #pragma unroll
                    for (int nt = 0; nt < 8; nt++)
                        #pragma unroll
                        for (int jj = 0; jj < 2; jj++) {
                            int n = n0 + nt * 8 + tq * 2 + jj;
                            float v = creg[mt][nt][rj * 2 + jj] + bias;
                            if (!p) v *= 0.125f;
                            __nv_bfloat16 h = __float2bfloat16(v);
                            __nv_bfloat16 l = __float2bfloat16(v - __bfloat162float(h));
                            uint32_t off = SWZ128((uint32_t)(n * 128 + d * 2));
                            *(__nv_bfloat16*)(dh + off) = h;
                            *(__nv_bfloat16*)(dl + off) = l;
                        }
                }
        }
        __syncthreads();
    }

    // ================= Phase 2: scores + softmax + w reduction =================
    {
        const int head = w >> 2;
        const int sb0  = (w & 3) * 32;
        const uint32_t qh = sbase + QT_H + head * 16384;
        const uint32_t ql = sbase + QT_L + head * 16384;
        const uint32_t kh = sbase + KT_H + head * 16384;
        const uint32_t kl = sbase + KT_L + head * 16384;

        float wacc[16][2];
        #pragma unroll
        for (int nt = 0; nt < 16; nt++) { wacc[nt][0] = 0.f; wacc[nt][1] = 0.f; }

        #pragma unroll 1
        for (int chunk = 0; chunk < 2; chunk++) {
            const int s0 = sb0 + chunk * 16;
            float sc[16][4];
            #pragma unroll
            for (int nt = 0; nt < 16; nt++)
                #pragma unroll
                for (int j = 0; j < 4; j++) sc[nt][j] = 0.f;

            #pragma unroll
            for (int ks = 0; ks < 4; ks++) {
                const int k0 = ks * 16;
                uint32_t aH[4], aL[4];
                {
                    int row = s0 + (lid & 15);
                    int col = k0 + ((lid >> 4) << 3);
                    uint32_t off = SWZ128((uint32_t)(row * 128 + col * 2));
                    ldsm4(aH, qh + off);
                    ldsm4(aL, ql + off);
                }
                #pragma unroll
                for (int np = 0; np < 8; np++) {
                    int tL   = lid >> 3;
                    int rrow = np * 16 + ((tL >> 1) << 3) + (lid & 7);
                    int ccol = k0 + ((tL & 1) << 3);
                    uint32_t off = SWZ128((uint32_t)(rrow * 128 + ccol * 2));
                    uint32_t bH[4], bLr[4];
                    ldsm4(bH, kh + off);
                    ldsm4(bLr, kl + off);
                    mma16816(sc[np * 2],     aH, bH[0],  bH[1]);
                    mma16816(sc[np * 2],     aH, bLr[0], bLr[1]);
                    mma16816(sc[np * 2],     aL, bH[0],  bH[1]);
                    mma16816(sc[np * 2 + 1], aH, bH[2],  bH[3]);
                    mma16816(sc[np * 2 + 1], aH, bLr[2], bLr[3]);
                    mma16816(sc[np * 2 + 1], aL, bH[2],  bH[3]);
                }
            }
            float mx0 = -1e30f, mx1 = -1e30f;
            #pragma unroll
            for (int nt = 0; nt < 16; nt++) {
                mx0 = fmaxf(mx0, fmaxf(sc[nt][0], sc[nt][1]));
                mx1 = fmaxf(mx1, fmaxf(sc[nt][2], sc[nt][3]));
            }
            mx0 = fmaxf(mx0, __shfl_xor_sync(0xffffffffu, mx0, 1));
            mx0 = fmaxf(mx0, __shfl_xor_sync(0xffffffffu, mx0, 2));
            mx1 = fmaxf(mx1, __shfl_xor_sync(0xffffffffu, mx1, 1));
            mx1 = fmaxf(mx1, __shfl_xor_sync(0xffffffffu, mx1, 2));
            float Z0 = 0.f, Z1 = 0.f;
            #pragma unroll
            for (int nt = 0; nt < 16; nt++) {
                sc[nt][0] = __expf(sc[nt][0] - mx0); Z0 += sc[nt][0];
                sc[nt][1] = __expf(sc[nt][1] - mx0); Z0 += sc[nt][1];
                sc[nt][2] = __expf(sc[nt][2] - mx1); Z1 += sc[nt][2];
                sc[nt][3] = __expf(sc[nt][3] - mx1); Z1 += sc[nt][3];
            }
            Z0 += __shfl_xor_sync(0xffffffffu, Z0, 1);
            Z0 += __shfl_xor_sync(0xffffffffu, Z0, 2);
            Z1 += __shfl_xor_sync(0xffffffffu, Z1, 1);
            Z1 += __shfl_xor_sync(0xffffffffu, Z1, 2);
            const float c0 = wos[s0 + gq]     / Z0;
            const float c1 = wos[s0 + 8 + gq] / Z1;
            #pragma unroll
            for (int nt = 0; nt < 16; nt++) {
                wacc[nt][0] += sc[nt][0] * c0 + sc[nt][2] * c1;
                wacc[nt][1] += sc[nt][1] * c0 + sc[nt][3] * c1;
            }
        }
        #pragma unroll
        for (int d = 4; d < 32; d <<= 1)
            #pragma unroll
            for (int nt = 0; nt < 16; nt++) {
                wacc[nt][0] += __shfl_xor_sync(0xffffffffu, wacc[nt][0], d);
                wacc[nt][1] += __shfl_xor_sync(0xffffffffu, wacc[nt][1], d);
            }
        if (lid < 4) {
            #pragma unroll
            for (int nt = 0; nt < 16; nt++) {
                atomicAdd(&wsm[head * 128 + nt * 8 + 2 * lid],     wacc[nt][0]);
                atomicAdd(&wsm[head * 128 + nt * 8 + 2 * lid + 1], wacc[nt][1]);
            }
        }
    }
    __syncthreads();

    // ================= Phase 3: out[b, g*128+f] = sum_t w[head][t] * x[b,f,t] + bo
    if (tid < 128) {
        const float* wv2 = wsm + (tid >> 6) * 128;
        const float4* x4 = (const float4*)(xb + (size_t)(g * 128 + tid) * SEQ);
        float acc = 0.f;
        #pragma unroll 8
        for (int t4 = 0; t4 < 32; t4++) {
            float4 xvv = x4[t4];
            acc += xvv.x * wv2[t4 * 4 + 0] + xvv.y * wv2[t4 * 4 + 1]
                 + xvv.z * wv2[t4 * 4 + 2] + xvv.w * wv2[t4 * 4 + 3];
        }
        out[(size_t)b * FIN + g * 128 + tid] = acc + bo[0];
    }
}

extern "C" void kernel_launch(void* const* d_in, const int* in_sizes, int n_in,
                              void* d_out, int out_size)
{
    (void)in_sizes; (void)n_in; (void)out_size;
    const float* x  = (const float*)d_in[0];
    const float* Wq = (const float*)d_in[1];
    const float* bq = (const float*)d_in[2];
    const float* Wk = (const float*)d_in[3];
    const float* bk = (const float*)d_in[4];
    const float* Wo = (const float*)d_in[5];
    const float* bo = (const float*)d_in[6];
    float* out = (float*)d_out;

    prep_w_kernel<<<1024, 256>>>(Wq, Wk);
    prep_x_kernel<<<32768, 256>>>(x);

    cudaFuncSetAttribute(Attention_75402445849133_kernel,
                         cudaFuncAttributeMaxDynamicSharedMemorySize, SMEM_TOTAL);
    dim3 grid(8, 256, 1);
    Attention_75402445849133_kernel<<<grid, 256, SMEM_TOTAL>>>(x, bq, bk, Wo, bo, out);
}

// round 7
// speedup vs baseline: 1.5045x; 1.1299x over previous
#include <cuda_runtime.h>
#include <cuda_bf16.h>
#include <cstdint>

// ============ sm_103-safe primitives ============
__device__ __forceinline__ uint32_t smem_u32(const void* p) {
    uint32_t a;
    asm("{ .reg .u64 t; cvta.to.shared.u64 t, %1; cvt.u32.u64 %0, t; }" : "=r"(a) : "l"(p));
    return a;
}
__device__ __forceinline__ void ldsm4(uint32_t r[4], uint32_t addr) {
    asm volatile("ldmatrix.sync.aligned.m8n8.x4.shared.b16 {%0,%1,%2,%3}, [%4];"
                 : "=r"(r[0]), "=r"(r[1]), "=r"(r[2]), "=r"(r[3]) : "r"(addr));
}
__device__ __forceinline__ void ldsm4t(uint32_t r[4], uint32_t addr) {
    asm volatile("ldmatrix.sync.aligned.m8n8.x4.trans.shared.b16 {%0,%1,%2,%3}, [%4];"
                 : "=r"(r[0]), "=r"(r[1]), "=r"(r[2]), "=r"(r[3]) : "r"(addr));
}
__device__ __forceinline__ void mma16816(float c[4], const uint32_t a[4],
                                         uint32_t b0, uint32_t b1) {
    asm volatile(
        "mma.sync.aligned.m16n8k16.row.col.f32.bf16.bf16.f32 "
        "{%0,%1,%2,%3},{%4,%5,%6,%7},{%8,%9},{%0,%1,%2,%3};"
        : "+f"(c[0]), "+f"(c[1]), "+f"(c[2]), "+f"(c[3])
        : "r"(a[0]), "r"(a[1]), "r"(a[2]), "r"(a[3]), "r"(b0), "r"(b1));
}
__device__ __forceinline__ uint32_t pack2(__nv_bfloat16 lo, __nv_bfloat16 hi) {
    return ((uint32_t)__bfloat16_as_ushort(hi) << 16) | (uint32_t)__bfloat16_as_ushort(lo);
}
__device__ __forceinline__ void split4(float4 v, uint2& h, uint2& l) {
    __nv_bfloat16 h0 = __float2bfloat16(v.x), h1 = __float2bfloat16(v.y);
    __nv_bfloat16 h2 = __float2bfloat16(v.z), h3 = __float2bfloat16(v.w);
    __nv_bfloat16 l0 = __float2bfloat16(v.x - __bfloat162float(h0));
    __nv_bfloat16 l1 = __float2bfloat16(v.y - __bfloat162float(h1));
    __nv_bfloat16 l2 = __float2bfloat16(v.z - __bfloat162float(h2));
    __nv_bfloat16 l3 = __float2bfloat16(v.w - __bfloat162float(h3));
    h = make_uint2(pack2(h0, h1), pack2(h2, h3));
    l = make_uint2(pack2(l0, l1), pack2(l2, l3));
}
__device__ __forceinline__ void cpa16(uint32_t dst, const void* src) {
    asm volatile("cp.async.cg.shared.global [%0], [%1], 16;" :: "r"(dst), "l"(src) : "memory");
}
#define CP_COMMIT() asm volatile("cp.async.commit_group;" ::: "memory")
#define CP_WAIT1()  asm volatile("cp.async.wait_group 1;" ::: "memory")
#define CP_WAIT0()  asm volatile("cp.async.wait_group 0;" ::: "memory")
// A tile: 64B rows; XOR row bits[6:8] into bank bits[4:6] -> 8 conflict-free rows
#define SWZ64A(o) ((o) ^ (((o) >> 2) & 0x70))
#define SWZ128(o) ((o) ^ (((o) >> 3) & 0x70))
#define SWZ256(o) ((o) ^ (((o) >> 4) & 0x70))

// ============ problem constants ============
#define FIN  1024
#define SEQ  128
#define CH   32
#define NC   32

// ============ pre-split global staging (bf16 hi/lo) ============
__device__ __align__(16) __nv_bfloat16 g_WqH[1024 * 1024];
__device__ __align__(16) __nv_bfloat16 g_WqL[1024 * 1024];
__device__ __align__(16) __nv_bfloat16 g_WkH[1024 * 1024];
__device__ __align__(16) __nv_bfloat16 g_WkL[1024 * 1024];
__device__ __align__(16) __nv_bfloat16 g_xH[256 * 1024 * 128];
__device__ __align__(16) __nv_bfloat16 g_xL[256 * 1024 * 128];

__global__ void __launch_bounds__(256) prep_w_kernel(const float* __restrict__ Wq,
                                                     const float* __restrict__ Wk) {
    int i = blockIdx.x * 256 + threadIdx.x;
    float4 v = ((const float4*)Wq)[i];
    uint2 h, l;
    split4(v, h, l);
    ((uint2*)g_WqH)[i] = h; ((uint2*)g_WqL)[i] = l;
    v = ((const float4*)Wk)[i];
    split4(v, h, l);
    ((uint2*)g_WkH)[i] = h; ((uint2*)g_WkL)[i] = l;
}
__global__ void __launch_bounds__(256) prep_x_kernel(const float* __restrict__ x) {
    size_t i = (size_t)blockIdx.x * 256 + threadIdx.x;
    float4 v = ((const float4*)x)[i];
    uint2 h, l;
    split4(v, h, l);
    ((uint2*)g_xH)[i] = h; ((uint2*)g_xL)[i] = l;
}

// ============ SMEM layout (bytes) ============
// chunk buffer (x2): [W 256x32 hi 16K | W lo 16K | x 32x128 hi 8K | x lo 8K] = 48K
#define BUF_SZ  49152
#define BW_H    0
#define BW_L    16384
#define BX_H    32768
#define BX_L    40960
// KT_L overlays the (dead after mainloop) chunk-buffer region
#define KT_L    0
#define QT_H    98304
#define QT_L    131072
#define KT_H    163840
#define W_SM    196608
#define BQ_SM   197632
#define BK_SM   198144
#define WO_SM   198656
#define SMEM_TOTAL 199168

__global__ void __launch_bounds__(256, 1)
Attention_75402445849133_kernel(const float* __restrict__ x,
                                const float* __restrict__ bq, const float* __restrict__ bk,
                                const float* __restrict__ Wo, const float* __restrict__ bo,
                                float* __restrict__ out)
{
    extern __shared__ char smem[];
    const uint32_t sbase = smem_u32(smem);
    const int tid = threadIdx.x;
    const int w   = tid >> 5;
    const int lid = tid & 31;
    const int gq  = lid >> 2;
    const int tq  = lid & 3;
    const int g   = blockIdx.x;
    const int b   = blockIdx.y;

    float* wsm = (float*)(smem + W_SM);
    float* bqs = (float*)(smem + BQ_SM);
    float* bks = (float*)(smem + BK_SM);
    float* wos = (float*)(smem + WO_SM);
    if (tid < 128) {
        bqs[tid] = bq[g * 128 + tid];
        bks[tid] = bk[g * 128 + tid];
        wos[tid] = Wo[tid];
    }
    wsm[tid] = 0.0f;

    const float* xb = x + (size_t)b * FIN * SEQ;
    const __nv_bfloat16* xbH = g_xH + (size_t)b * FIN * SEQ;
    const __nv_bfloat16* xbL = g_xL + (size_t)b * FIN * SEQ;

    // MMA warp tiling: 256 (q128|k128 stacked) x 128, 8 warps of 64x64
    const int m0 = (w & 3) * 64;
    const int n0 = (w >> 2) * 64;

    // ---- cp.async coordinates ----
    // W: 1024 granules (row 0..255, col grp 0..3), thread handles j*256+tid
    const __nv_bfloat16* wbH[4];
    const __nv_bfloat16* wbL[4];
    uint32_t wsoff[4];
    #pragma unroll
    for (int j = 0; j < 4; j++) {
        int wi = j * 256 + tid;
        int row = wi >> 2, cg = wi & 3;
        wsoff[j] = SWZ64A((uint32_t)(row * 64 + cg * 16));
        int isq = (row < 128);
        int rl  = row & 127;
        wbH[j] = (isq ? g_WqH : g_WkH) + (size_t)(g * 128 + rl) * FIN + cg * 8;
        wbL[j] = (isq ? g_WqL : g_WkL) + (size_t)(g * 128 + rl) * FIN + cg * 8;
    }
    // x: 512 granules (k row 0..31, seg 0..15)
    uint32_t xsoff[2];
    int xrr[2], xsg[2];
    #pragma unroll
    for (int j = 0; j < 2; j++) {
        int xi = j * 256 + tid;
        xrr[j] = xi >> 4; xsg[j] = xi & 15;
        xsoff[j] = SWZ256((uint32_t)(xrr[j] * 256 + xsg[j] * 16));
    }

    float creg[4][8][4];
    #pragma unroll
    for (int a = 0; a < 4; a++)
        #pragma unroll
        for (int n = 0; n < 8; n++)
            #pragma unroll
            for (int j = 0; j < 4; j++) creg[a][n][j] = 0.f;

    // prologue: issue chunk 0
    #pragma unroll
    for (int j = 0; j < 4; j++) {
        cpa16(sbase + BW_H + wsoff[j], wbH[j]);
        cpa16(sbase + BW_L + wsoff[j], wbL[j]);
    }
    #pragma unroll
    for (int j = 0; j < 2; j++) {
        cpa16(sbase + BX_H + xsoff[j], xbH + xrr[j] * SEQ + xsg[j] * 8);
        cpa16(sbase + BX_L + xsoff[j], xbL + xrr[j] * SEQ + xsg[j] * 8);
    }
    CP_COMMIT();

    // ================= fused Q+K projection mainloop =================
    #pragma unroll 1
    for (int kc = 0; kc < NC; kc++) {
        if (kc + 1 < NC) {
            const uint32_t nb = sbase + ((kc + 1) & 1) * BUF_SZ;
            const int kn = (kc + 1) * CH;
            #pragma unroll
            for (int j = 0; j < 4; j++) {
                cpa16(nb + BW_H + wsoff[j], wbH[j] + kn);
                cpa16(nb + BW_L + wsoff[j], wbL[j] + kn);
            }
            #pragma unroll
            for (int j = 0; j < 2; j++) {
                cpa16(nb + BX_H + xsoff[j], xbH + (size_t)(kn + xrr[j]) * SEQ + xsg[j] * 8);
                cpa16(nb + BX_L + xsoff[j], xbL + (size_t)(kn + xrr[j]) * SEQ + xsg[j] * 8);
            }
            CP_COMMIT();
            CP_WAIT1();
        } else {
            CP_WAIT0();
        }
        __syncthreads();

        const uint32_t bufb = sbase + (kc & 1) * BUF_SZ;
        #pragma unroll
        for (int ks = 0; ks < 2; ks++) {
            const int k0 = ks * 16;
            uint32_t aH[4][4], aL[4][4];
            #pragma unroll
            for (int mt = 0; mt < 4; mt++) {
                int row = m0 + mt * 16 + (lid & 15);
                int col = k0 + ((lid >> 4) << 3);
                uint32_t off = SWZ64A((uint32_t)(row * 64 + col * 2));
                ldsm4(aH[mt], bufb + BW_H + off);
                ldsm4(aL[mt], bufb + BW_L + off);
            }
            #pragma unroll
            for (int np = 0; np < 4; np++) {
                int tL  = lid >> 3;
                int krw = k0 + ((tL & 1) << 3) + (lid & 7);
                int nc  = n0 + np * 16 + ((tL >> 1) << 3);
                uint32_t off = SWZ256((uint32_t)(krw * 256 + nc * 2));
                uint32_t bH[4], bL[4];
                ldsm4t(bH, bufb + BX_H + off);
                ldsm4t(bL, bufb + BX_L + off);
                #pragma unroll
                for (int mt = 0; mt < 4; mt++) {
                    mma16816(creg[mt][np * 2],     aH[mt], bH[0], bH[1]);
                    mma16816(creg[mt][np * 2],     aH[mt], bL[0], bL[1]);
                    mma16816(creg[mt][np * 2],     aL[mt], bH[0], bH[1]);
                    mma16816(creg[mt][np * 2 + 1], aH[mt], bH[2], bH[3]);
                    mma16816(creg[mt][np * 2 + 1], aH[mt], bL[2], bL[3]);
                    mma16816(creg[mt][np * 2 + 1], aL[mt], bH[2], bH[3]);
                }
            }
        }
        __syncthreads();
    }

    // ---- writeback: stacked C -> qT / kT split bf16 (+bias; q scaled 1/8) ----
    {
        #pragma unroll
        for (int mt = 0; mt < 4; mt++)
            #pragma unroll
            for (int rj = 0; rj < 2; rj++) {
                int m = m0 + mt * 16 + rj * 8 + gq;     // 0..255 stacked
                int isq = (m < 128);
                int mloc = m & 127;
                float bias = isq ? bqs[mloc] : bks[mloc];
                int head = mloc >> 6, d = mloc & 63;
                char* dh = smem + (isq ? QT_H : KT_H) + head * 16384;
                char* dl = smem + (isq ? QT_L : KT_L) + head * 16384;
                #pragma unroll
                for (int nt = 0; nt < 8; nt++)
                    #pragma unroll
                    for (int jj = 0; jj < 2; jj++) {
                        int n = n0 + nt * 8 + tq * 2 + jj;
                        float v = creg[mt][nt][rj * 2 + jj] + bias;
                        if (isq) v *= 0.125f;
                        __nv_bfloat16 h = __float2bfloat16(v);
                        __nv_bfloat16 l = __float2bfloat16(v - __bfloat162float(h));
                        uint32_t off = SWZ128((uint32_t)(n * 128 + d * 2));
                        *(__nv_bfloat16*)(dh + off) = h;
                        *(__nv_bfloat16*)(dl + off) = l;
                    }
            }
    }
    __syncthreads();

    // ================= Phase 2: scores + softmax + w reduction =================
    {
        const int head = w >> 2;
        const int sb0  = (w & 3) * 32;
        const uint32_t qh = sbase + QT_H + head * 16384;
        const uint32_t ql = sbase + QT_L + head * 16384;
        const uint32_t kh = sbase + KT_H + head * 16384;
        const uint32_t kl = sbase + KT_L + head * 16384;

        float wacc[16][2];
        #pragma unroll
        for (int nt = 0; nt < 16; nt++) { wacc[nt][0] = 0.f; wacc[nt][1] = 0.f; }

        #pragma unroll 1
        for (int chunk = 0; chunk < 2; chunk++) {
            const int s0 = sb0 + chunk * 16;
            float sc[16][4];
            #pragma unroll
            for (int nt = 0; nt < 16; nt++)
                #pragma unroll
                for (int j = 0; j < 4; j++) sc[nt][j] = 0.f;

            #pragma unroll
            for (int ks = 0; ks < 4; ks++) {
                const int k0 = ks * 16;
                uint32_t aH[4], aL[4];
                {
                    int row = s0 + (lid & 15);
                    int col = k0 + ((lid >> 4) << 3);
                    uint32_t off = SWZ128((uint32_t)(row * 128 + col * 2));
                    ldsm4(aH, qh + off);
                    ldsm4(aL, ql + off);
                }
                #pragma unroll
                for (int np = 0; np < 8; np++) {
                    int tL   = lid >> 3;
                    int rrow = np * 16 + ((tL >> 1) << 3) + (lid & 7);
                    int ccol = k0 + ((tL & 1) << 3);
                    uint32_t off = SWZ128((uint32_t)(rrow * 128 + ccol * 2));
                    uint32_t bH[4], bLr[4];
                    ldsm4(bH, kh + off);
                    ldsm4(bLr, kl + off);
                    mma16816(sc[np * 2],     aH, bH[0],  bH[1]);
                    mma16816(sc[np * 2],     aH, bLr[0], bLr[1]);
                    mma16816(sc[np * 2],     aL, bH[0],  bH[1]);
                    mma16816(sc[np * 2 + 1], aH, bH[2],  bH[3]);
                    mma16816(sc[np * 2 + 1], aH, bLr[2], bLr[3]);
                    mma16816(sc[np * 2 + 1], aL, bH[2],  bH[3]);
                }
            }
            float mx0 = -1e30f, mx1 = -1e30f;
            #pragma unroll
            for (int nt = 0; nt < 16; nt++) {
                mx0 = fmaxf(mx0, fmaxf(sc[nt][0], sc[nt][1]));
                mx1 = fmaxf(mx1, fmaxf(sc[nt][2], sc[nt][3]));
            }
            mx0 = fmaxf(mx0, __shfl_xor_sync(0xffffffffu, mx0, 1));
            mx0 = fmaxf(mx0, __shfl_xor_sync(0xffffffffu, mx0, 2));
            mx1 = fmaxf(mx1, __shfl_xor_sync(0xffffffffu, mx1, 1));
            mx1 = fmaxf(mx1, __shfl_xor_sync(0xffffffffu, mx1, 2));
            float Z0 = 0.f, Z1 = 0.f;
            #pragma unroll
            for (int nt = 0; nt < 16; nt++) {
                sc[nt][0] = __expf(sc[nt][0] - mx0); Z0 += sc[nt][0];
                sc[nt][1] = __expf(sc[nt][1] - mx0); Z0 += sc[nt][1];
                sc[nt][2] = __expf(sc[nt][2] - mx1); Z1 += sc[nt][2];
                sc[nt][3] = __expf(sc[nt][3] - mx1); Z1 += sc[nt][3];
            }
            Z0 += __shfl_xor_sync(0xffffffffu, Z0, 1);
            Z0 += __shfl_xor_sync(0xffffffffu, Z0, 2);
            Z1 += __shfl_xor_sync(0xffffffffu, Z1, 1);
            Z1 += __shfl_xor_sync(0xffffffffu, Z1, 2);
            const float c0 = wos[s0 + gq]     / Z0;
            const float c1 = wos[s0 + 8 + gq] / Z1;
            #pragma unroll
            for (int nt = 0; nt < 16; nt++) {
                wacc[nt][0] += sc[nt][0] * c0 + sc[nt][2] * c1;
                wacc[nt][1] += sc[nt][1] * c0 + sc[nt][3] * c1;
            }
        }
        #pragma unroll
        for (int d = 4; d < 32; d <<= 1)
            #pragma unroll
            for (int nt = 0; nt < 16; nt++) {
                wacc[nt][0] += __shfl_xor_sync(0xffffffffu, wacc[nt][0], d);
                wacc[nt][1] += __shfl_xor_sync(0xffffffffu, wacc[nt][1], d);
            }
        if (lid < 4) {
            #pragma unroll
            for (int nt = 0; nt < 16; nt++) {
                atomicAdd(&wsm[head * 128 + nt * 8 + 2 * lid],     wacc[nt][0]);
                atomicAdd(&wsm[head * 128 + nt * 8 + 2 * lid + 1], wacc[nt][1]);
            }
        }
    }
    __syncthreads();

    // ================= Phase 3: out[b, g*128+f] = sum_t w[head][t]*x[b,f,t] + bo
    if (tid < 128) {
        const float* wv2 = wsm + (tid >> 6) * 128;
        const float4* x4 = (const float4*)(xb + (size_t)(g * 128 + tid) * SEQ);
        float acc = 0.f;
        #pragma unroll 8
        for (int t4 = 0; t4 < 32; t4++) {
            float4 xvv = x4[t4];
            acc += xvv.x * wv2[t4 * 4 + 0] + xvv.y * wv2[t4 * 4 + 1]
                 + xvv.z * wv2[t4 * 4 + 2] + xvv.w * wv2[t4 * 4 + 3];
        }
        out[(size_t)b * FIN + g * 128 + tid] = acc + bo[0];
    }
}

extern "C" void kernel_launch(void* const* d_in, const int* in_sizes, int n_in,
                              void* d_out, int out_size)
{
    (void)in_sizes; (void)n_in; (void)out_size;
    const float* x  = (const float*)d_in[0];
    const float* Wq = (const float*)d_in[1];
    const float* bq = (const float*)d_in[2];
    const float* Wk = (const float*)d_in[3];
    const float* bk = (const float*)d_in[4];
    const float* Wo = (const float*)d_in[5];
    const float* bo = (const float*)d_in[6];
    float* out = (float*)d_out;

    prep_w_kernel<<<1024, 256>>>(Wq, Wk);
    prep_x_kernel<<<32768, 256>>>(x);

    cudaFuncSetAttribute(Attention_75402445849133_kernel,
                         cudaFuncAttributeMaxDynamicSharedMemorySize, SMEM_TOTAL);
    dim3 grid(8, 256, 1);
    Attention_75402445849133_kernel<<<grid, 256, SMEM_TOTAL>>>(x, bq, bk, Wo, bo, out);
}

// round 8
// speedup vs baseline: 1.9557x; 1.2998x over previous
#include <cuda_runtime.h>
#include <cuda_fp16.h>
#include <cstdint>

// ============ sm_103-safe primitives ============
__device__ __forceinline__ uint32_t smem_u32(const void* p) {
    uint32_t a;
    asm("{ .reg .u64 t; cvta.to.shared.u64 t, %1; cvt.u32.u64 %0, t; }" : "=r"(a) : "l"(p));
    return a;
}
__device__ __forceinline__ void ldsm4(uint32_t r[4], uint32_t addr) {
    asm volatile("ldmatrix.sync.aligned.m8n8.x4.shared.b16 {%0,%1,%2,%3}, [%4];"
                 : "=r"(r[0]), "=r"(r[1]), "=r"(r[2]), "=r"(r[3]) : "r"(addr));
}
__device__ __forceinline__ void ldsm4t(uint32_t r[4], uint32_t addr) {
    asm volatile("ldmatrix.sync.aligned.m8n8.x4.trans.shared.b16 {%0,%1,%2,%3}, [%4];"
                 : "=r"(r[0]), "=r"(r[1]), "=r"(r[2]), "=r"(r[3]) : "r"(addr));
}
__device__ __forceinline__ void mma16816(float c[4], const uint32_t a[4],
                                         uint32_t b0, uint32_t b1) {
    asm volatile(
        "mma.sync.aligned.m16n8k16.row.col.f32.f16.f16.f32 "
        "{%0,%1,%2,%3},{%4,%5,%6,%7},{%8,%9},{%0,%1,%2,%3};"
        : "+f"(c[0]), "+f"(c[1]), "+f"(c[2]), "+f"(c[3])
        : "r"(a[0]), "r"(a[1]), "r"(a[2]), "r"(a[3]), "r"(b0), "r"(b1));
}
__device__ __forceinline__ uint32_t pack2h(__half lo, __half hi) {
    return ((uint32_t)__half_as_ushort(hi) << 16) | (uint32_t)__half_as_ushort(lo);
}
// fp32 -> fp16 hi + fp16 lo residual
__device__ __forceinline__ void split4h(float4 v, uint2& h, uint2& l) {
    __half h0 = __float2half_rn(v.x), h1 = __float2half_rn(v.y);
    __half h2 = __float2half_rn(v.z), h3 = __float2half_rn(v.w);
    __half l0 = __float2half_rn(v.x - __half2float(h0));
    __half l1 = __float2half_rn(v.y - __half2float(h1));
    __half l2 = __float2half_rn(v.z - __half2float(h2));
    __half l3 = __float2half_rn(v.w - __half2float(h3));
    h = make_uint2(pack2h(h0, h1), pack2h(h2, h3));
    l = make_uint2(pack2h(l0, l1), pack2h(l2, l3));
}
__device__ __forceinline__ uint2 cvt4h(float4 v) {
    return make_uint2(pack2h(__float2half_rn(v.x), __float2half_rn(v.y)),
                      pack2h(__float2half_rn(v.z), __float2half_rn(v.w)));
}
__device__ __forceinline__ void cpa16(uint32_t dst, const void* src) {
    asm volatile("cp.async.cg.shared.global [%0], [%1], 16;" :: "r"(dst), "l"(src) : "memory");
}
#define CP_COMMIT() asm volatile("cp.async.commit_group;" ::: "memory")
#define CP_WAIT1()  asm volatile("cp.async.wait_group 1;" ::: "memory")
#define CP_WAIT0()  asm volatile("cp.async.wait_group 0;" ::: "memory")
#define SWZ64A(o) ((o) ^ (((o) >> 2) & 0x70))
#define SWZ128(o) ((o) ^ (((o) >> 3) & 0x70))
#define SWZ256(o) ((o) ^ (((o) >> 4) & 0x70))

// ============ problem constants ============
#define FIN  1024
#define SEQ  128
#define CH   32
#define NC   32

// ============ pre-split global staging (fp16) ============
__device__ __align__(16) __half g_WqH[1024 * 1024];
__device__ __align__(16) __half g_WqL[1024 * 1024];
__device__ __align__(16) __half g_WkH[1024 * 1024];
__device__ __align__(16) __half g_WkL[1024 * 1024];
__device__ __align__(16) __half g_x[256 * 1024 * 128];

__global__ void __launch_bounds__(256) prep_w_kernel(const float* __restrict__ Wq,
                                                     const float* __restrict__ Wk) {
    int i = blockIdx.x * 256 + threadIdx.x;
    float4 v = ((const float4*)Wq)[i];
    uint2 h, l;
    split4h(v, h, l);
    ((uint2*)g_WqH)[i] = h; ((uint2*)g_WqL)[i] = l;
    v = ((const float4*)Wk)[i];
    split4h(v, h, l);
    ((uint2*)g_WkH)[i] = h; ((uint2*)g_WkL)[i] = l;
}
__global__ void __launch_bounds__(256) prep_x_kernel(const float* __restrict__ x) {
    size_t i = (size_t)blockIdx.x * 256 + threadIdx.x;
    ((uint2*)g_x)[i] = cvt4h(((const float4*)x)[i]);
}

// ============ SMEM layout (bytes) ============
// chunk buffer (x2): [Wh 256x32 16K | Wl 16K | x 32x128 8K] = 40K
#define BUF_SZ  40960
#define BW_H    0
#define BW_L    16384
#define BX_S    32768
// KT_L overlays the (dead after mainloop) chunk-buffer region
#define KT_L    0
#define QT_H    81920
#define QT_L    114688
#define KT_H    147456
#define W_SM    180224
#define BQ_SM   181248
#define BK_SM   181760
#define WO_SM   182272
#define SMEM_TOTAL 182784

__global__ void __launch_bounds__(256, 1)
Attention_75402445849133_kernel(const float* __restrict__ x,
                                const float* __restrict__ bq, const float* __restrict__ bk,
                                const float* __restrict__ Wo, const float* __restrict__ bo,
                                float* __restrict__ out)
{
    extern __shared__ char smem[];
    const uint32_t sbase = smem_u32(smem);
    const int tid = threadIdx.x;
    const int w   = tid >> 5;
    const int lid = tid & 31;
    const int gq  = lid >> 2;
    const int tq  = lid & 3;
    const int g   = blockIdx.x;
    const int b   = blockIdx.y;

    float* wsm = (float*)(smem + W_SM);
    float* bqs = (float*)(smem + BQ_SM);
    float* bks = (float*)(smem + BK_SM);
    float* wos = (float*)(smem + WO_SM);
    if (tid < 128) {
        bqs[tid] = bq[g * 128 + tid];
        bks[tid] = bk[g * 128 + tid];
        wos[tid] = Wo[tid];
    }
    wsm[tid] = 0.0f;

    const float* xb = x + (size_t)b * FIN * SEQ;
    const __half* xbh = g_x + (size_t)b * FIN * SEQ;

    // MMA warp tiling: 256 (q128|k128 stacked) x 128, 8 warps of 64x64
    const int m0 = (w & 3) * 64;
    const int n0 = (w >> 2) * 64;

    // ---- cp.async coordinates ----
    const __half* wbH[4];
    const __half* wbL[4];
    uint32_t wsoff[4];
    #pragma unroll
    for (int j = 0; j < 4; j++) {
        int wi = j * 256 + tid;
        int row = wi >> 2, cg = wi & 3;
        wsoff[j] = SWZ64A((uint32_t)(row * 64 + cg * 16));
        int isq = (row < 128);
        int rl  = row & 127;
        wbH[j] = (isq ? g_WqH : g_WkH) + (size_t)(g * 128 + rl) * FIN + cg * 8;
        wbL[j] = (isq ? g_WqL : g_WkL) + (size_t)(g * 128 + rl) * FIN + cg * 8;
    }
    uint32_t xsoff[2];
    int xrr[2], xsg[2];
    #pragma unroll
    for (int j = 0; j < 2; j++) {
        int xi = j * 256 + tid;
        xrr[j] = xi >> 4; xsg[j] = xi & 15;
        xsoff[j] = SWZ256((uint32_t)(xrr[j] * 256 + xsg[j] * 16));
    }

    float creg[4][8][4];
    #pragma unroll
    for (int a = 0; a < 4; a++)
        #pragma unroll
        for (int n = 0; n < 8; n++)
            #pragma unroll
            for (int j = 0; j < 4; j++) creg[a][n][j] = 0.f;

    // prologue: issue chunk 0
    #pragma unroll
    for (int j = 0; j < 4; j++) {
        cpa16(sbase + BW_H + wsoff[j], wbH[j]);
        cpa16(sbase + BW_L + wsoff[j], wbL[j]);
    }
    #pragma unroll
    for (int j = 0; j < 2; j++)
        cpa16(sbase + BX_S + xsoff[j], xbh + xrr[j] * SEQ + xsg[j] * 8);
    CP_COMMIT();

    // ================= fused Q+K projection mainloop (2 MMA terms) =============
    #pragma unroll 1
    for (int kc = 0; kc < NC; kc++) {
        if (kc + 1 < NC) {
            const uint32_t nb = sbase + ((kc + 1) & 1) * BUF_SZ;
            const int kn = (kc + 1) * CH;
            #pragma unroll
            for (int j = 0; j < 4; j++) {
                cpa16(nb + BW_H + wsoff[j], wbH[j] + kn);
                cpa16(nb + BW_L + wsoff[j], wbL[j] + kn);
            }
            #pragma unroll
            for (int j = 0; j < 2; j++)
                cpa16(nb + BX_S + xsoff[j], xbh + (size_t)(kn + xrr[j]) * SEQ + xsg[j] * 8);
            CP_COMMIT();
            CP_WAIT1();
        } else {
            CP_WAIT0();
        }
        __syncthreads();

        const uint32_t bufb = sbase + (kc & 1) * BUF_SZ;
        #pragma unroll
        for (int ks = 0; ks < 2; ks++) {
            const int k0 = ks * 16;
            uint32_t aH[4][4], aL[4][4];
            #pragma unroll
            for (int mt = 0; mt < 4; mt++) {
                int row = m0 + mt * 16 + (lid & 15);
                int col = k0 + ((lid >> 4) << 3);
                uint32_t off = SWZ64A((uint32_t)(row * 64 + col * 2));
                ldsm4(aH[mt], bufb + BW_H + off);
                ldsm4(aL[mt], bufb + BW_L + off);
            }
            #pragma unroll
            for (int np = 0; np < 4; np++) {
                int tL  = lid >> 3;
                int krw = k0 + ((tL & 1) << 3) + (lid & 7);
                int nc  = n0 + np * 16 + ((tL >> 1) << 3);
                uint32_t off = SWZ256((uint32_t)(krw * 256 + nc * 2));
                uint32_t bF[4];
                ldsm4t(bF, bufb + BX_S + off);
                #pragma unroll
                for (int mt = 0; mt < 4; mt++) {
                    mma16816(creg[mt][np * 2],     aH[mt], bF[0], bF[1]);
                    mma16816(creg[mt][np * 2],     aL[mt], bF[0], bF[1]);
                    mma16816(creg[mt][np * 2 + 1], aH[mt], bF[2], bF[3]);
                    mma16816(creg[mt][np * 2 + 1], aL[mt], bF[2], bF[3]);
                }
            }
        }
        __syncthreads();
    }

    // ---- writeback: stacked C -> qT / kT split fp16 (+bias; q scaled 1/8) ----
    {
        #pragma unroll
        for (int mt = 0; mt < 4; mt++)
            #pragma unroll
            for (int rj = 0; rj < 2; rj++) {
                int m = m0 + mt * 16 + rj * 8 + gq;
                int isq = (m < 128);
                int mloc = m & 127;
                float bias = isq ? bqs[mloc] : bks[mloc];
                int head = mloc >> 6, d = mloc & 63;
                char* dh = smem + (isq ? QT_H : KT_H) + head * 16384;
                char* dl = smem + (isq ? QT_L : KT_L) + head * 16384;
                #pragma unroll
                for (int nt = 0; nt < 8; nt++)
                    #pragma unroll
                    for (int jj = 0; jj < 2; jj++) {
                        int n = n0 + nt * 8 + tq * 2 + jj;
                        float v = creg[mt][nt][rj * 2 + jj] + bias;
                        if (isq) v *= 0.125f;
                        __half h = __float2half_rn(v);
                        __half l = __float2half_rn(v - __half2float(h));
                        uint32_t off = SWZ128((uint32_t)(n * 128 + d * 2));
                        *(__half*)(dh + off) = h;
                        *(__half*)(dl + off) = l;
                    }
            }
    }
    __syncthreads();

    // ================= Phase 2: scores (3-term fp16) + softmax + w reduction ====
    {
        const int head = w >> 2;
        const int sb0  = (w & 3) * 32;
        const uint32_t qh = sbase + QT_H + head * 16384;
        const uint32_t ql = sbase + QT_L + head * 16384;
        const uint32_t kh = sbase + KT_H + head * 16384;
        const uint32_t kl = sbase + KT_L + head * 16384;

        float wacc[16][2];
        #pragma unroll
        for (int nt = 0; nt < 16; nt++) { wacc[nt][0] = 0.f; wacc[nt][1] = 0.f; }

        #pragma unroll 1
        for (int chunk = 0; chunk < 2; chunk++) {
            const int s0 = sb0 + chunk * 16;
            float sc[16][4];
            #pragma unroll
            for (int nt = 0; nt < 16; nt++)
                #pragma unroll
                for (int j = 0; j < 4; j++) sc[nt][j] = 0.f;

            #pragma unroll
            for (int ks = 0; ks < 4; ks++) {
                const int k0 = ks * 16;
                uint32_t aH[4], aL[4];
                {
                    int row = s0 + (lid & 15);
                    int col = k0 + ((lid >> 4) << 3);
                    uint32_t off = SWZ128((uint32_t)(row * 128 + col * 2));
                    ldsm4(aH, qh + off);
                    ldsm4(aL, ql + off);
                }
                #pragma unroll
                for (int np = 0; np < 8; np++) {
                    int tL   = lid >> 3;
                    int rrow = np * 16 + ((tL >> 1) << 3) + (lid & 7);
                    int ccol = k0 + ((tL & 1) << 3);
                    uint32_t off = SWZ128((uint32_t)(rrow * 128 + ccol * 2));
                    uint32_t bH[4], bLr[4];
                    ldsm4(bH, kh + off);
                    ldsm4(bLr, kl + off);
                    mma16816(sc[np * 2],     aH, bH[0],  bH[1]);
                    mma16816(sc[np * 2],     aH, bLr[0], bLr[1]);
                    mma16816(sc[np * 2],     aL, bH[0],  bH[1]);
                    mma16816(sc[np * 2 + 1], aH, bH[2],  bH[3]);
                    mma16816(sc[np * 2 + 1], aH, bLr[2], bLr[3]);
                    mma16816(sc[np * 2 + 1], aL, bH[2],  bH[3]);
                }
            }
            float mx0 = -1e30f, mx1 = -1e30f;
            #pragma unroll
            for (int nt = 0; nt < 16; nt++) {
                mx0 = fmaxf(mx0, fmaxf(sc[nt][0], sc[nt][1]));
                mx1 = fmaxf(mx1, fmaxf(sc[nt][2], sc[nt][3]));
            }
            mx0 = fmaxf(mx0, __shfl_xor_sync(0xffffffffu, mx0, 1));
            mx0 = fmaxf(mx0, __shfl_xor_sync(0xffffffffu, mx0, 2));
            mx1 = fmaxf(mx1, __shfl_xor_sync(0xffffffffu, mx1, 1));
            mx1 = fmaxf(mx1, __shfl_xor_sync(0xffffffffu, mx1, 2));
            float Z0 = 0.f, Z1 = 0.f;
            #pragma unroll
            for (int nt = 0; nt < 16; nt++) {
                sc[nt][0] = __expf(sc[nt][0] - mx0); Z0 += sc[nt][0];
                sc[nt][1] = __expf(sc[nt][1] - mx0); Z0 += sc[nt][1];
                sc[nt][2] = __expf(sc[nt][2] - mx1); Z1 += sc[nt][2];
                sc[nt][3] = __expf(sc[nt][3] - mx1); Z1 += sc[nt][3];
            }
            Z0 += __shfl_xor_sync(0xffffffffu, Z0, 1);
            Z0 += __shfl_xor_sync(0xffffffffu, Z0, 2);
            Z1 += __shfl_xor_sync(0xffffffffu, Z1, 1);
            Z1 += __shfl_xor_sync(0xffffffffu, Z1, 2);
            const float c0 = wos[s0 + gq]     / Z0;
            const float c1 = wos[s0 + 8 + gq] / Z1;
            #pragma unroll
            for (int nt = 0; nt < 16; nt++) {
                wacc[nt][0] += sc[nt][0] * c0 + sc[nt][2] * c1;
                wacc[nt][1] += sc[nt][1] * c0 + sc[nt][3] * c1;
            }
        }
        #pragma unroll
        for (int d = 4; d < 32; d <<= 1)
            #pragma unroll
            for (int nt = 0; nt < 16; nt++) {
                wacc[nt][0] += __shfl_xor_sync(0xffffffffu, wacc[nt][0], d);
                wacc[nt][1] += __shfl_xor_sync(0xffffffffu, wacc[nt][1], d);
            }
        if (lid < 4) {
            #pragma unroll
            for (int nt = 0; nt < 16; nt++) {
                atomicAdd(&wsm[head * 128 + nt * 8 + 2 * lid],     wacc[nt][0]);
                atomicAdd(&wsm[head * 128 + nt * 8 + 2 * lid + 1], wacc[nt][1]);
            }
        }
    }
    __syncthreads();

    // ================= Phase 3: out[b, g*128+f] = sum_t w[head][t]*x[b,f,t] + bo
    if (tid < 128) {
        const float* wv2 = wsm + (tid >> 6) * 128;
        const float4* x4 = (const float4*)(xb + (size_t)(g * 128 + tid) * SEQ);
        float acc = 0.f;
        #pragma unroll 8
        for (int t4 = 0; t4 < 32; t4++) {
            float4 xvv = x4[t4];
            acc += xvv.x * wv2[t4 * 4 + 0] + xvv.y * wv2[t4 * 4 + 1]
                 + xvv.z * wv2[t4 * 4 + 2] + xvv.w * wv2[t4 * 4 + 3];
        }
        out[(size_t)b * FIN + g * 128 + tid] = acc + bo[0];
    }
}

extern "C" void kernel_launch(void* const* d_in, const int* in_sizes, int n_in,
                              void* d_out, int out_size)
{
    (void)in_sizes; (void)n_in; (void)out_size;
    const float* x  = (const float*)d_in[0];
    const float* Wq = (const float*)d_in[1];
    const float* bq = (const float*)d_in[2];
    const float* Wk = (const float*)d_in[3];
    const float* bk = (const float*)d_in[4];
    const float* Wo = (const float*)d_in[5];
    const float* bo = (const float*)d_in[6];
    float* out = (float*)d_out;

    prep_w_kernel<<<1024, 256>>>(Wq, Wk);
    prep_x_kernel<<<32768, 256>>>(x);

    cudaFuncSetAttribute(Attention_75402445849133_kernel,
                         cudaFuncAttributeMaxDynamicSharedMemorySize, SMEM_TOTAL);
    dim3 grid(8, 256, 1);
    Attention_75402445849133_kernel<<<grid, 256, SMEM_TOTAL>>>(x, bq, bk, Wo, bo, out);
}

// round 9
// speedup vs baseline: 1.9579x; 1.0011x over previous
#include <cuda_runtime.h>
#include <cuda_fp16.h>
#include <cstdint>

// ============ sm_103-safe primitives ============
__device__ __forceinline__ uint32_t smem_u32(const void* p) {
    uint32_t a;
    asm("{ .reg .u64 t; cvta.to.shared.u64 t, %1; cvt.u32.u64 %0, t; }" : "=r"(a) : "l"(p));
    return a;
}
__device__ __forceinline__ void ldsm4(uint32_t r[4], uint32_t addr) {
    asm volatile("ldmatrix.sync.aligned.m8n8.x4.shared.b16 {%0,%1,%2,%3}, [%4];"
                 : "=r"(r[0]), "=r"(r[1]), "=r"(r[2]), "=r"(r[3]) : "r"(addr));
}
__device__ __forceinline__ void ldsm4t(uint32_t r[4], uint32_t addr) {
    asm volatile("ldmatrix.sync.aligned.m8n8.x4.trans.shared.b16 {%0,%1,%2,%3}, [%4];"
                 : "=r"(r[0]), "=r"(r[1]), "=r"(r[2]), "=r"(r[3]) : "r"(addr));
}
__device__ __forceinline__ void mma16816(float c[4], const uint32_t a[4],
                                         uint32_t b0, uint32_t b1) {
    asm volatile(
        "mma.sync.aligned.m16n8k16.row.col.f32.f16.f16.f32 "
        "{%0,%1,%2,%3},{%4,%5,%6,%7},{%8,%9},{%0,%1,%2,%3};"
        : "+f"(c[0]), "+f"(c[1]), "+f"(c[2]), "+f"(c[3])
        : "r"(a[0]), "r"(a[1]), "r"(a[2]), "r"(a[3]), "r"(b0), "r"(b1));
}
__device__ __forceinline__ uint32_t pack2h(__half lo, __half hi) {
    return ((uint32_t)__half_as_ushort(hi) << 16) | (uint32_t)__half_as_ushort(lo);
}
__device__ __forceinline__ void split4h(float4 v, uint2& h, uint2& l) {
    __half h0 = __float2half_rn(v.x), h1 = __float2half_rn(v.y);
    __half h2 = __float2half_rn(v.z), h3 = __float2half_rn(v.w);
    __half l0 = __float2half_rn(v.x - __half2float(h0));
    __half l1 = __float2half_rn(v.y - __half2float(h1));
    __half l2 = __float2half_rn(v.z - __half2float(h2));
    __half l3 = __float2half_rn(v.w - __half2float(h3));
    h = make_uint2(pack2h(h0, h1), pack2h(h2, h3));
    l = make_uint2(pack2h(l0, l1), pack2h(l2, l3));
}
__device__ __forceinline__ uint2 cvt4h(float4 v) {
    return make_uint2(pack2h(__float2half_rn(v.x), __float2half_rn(v.y)),
                      pack2h(__float2half_rn(v.z), __float2half_rn(v.w)));
}
__device__ __forceinline__ void cpa16(uint32_t dst, const void* src) {
    asm volatile("cp.async.cg.shared.global [%0], [%1], 16;" :: "r"(dst), "l"(src) : "memory");
}
#define CP_COMMIT() asm volatile("cp.async.commit_group;" ::: "memory")
#define CP_WAIT1()  asm volatile("cp.async.wait_group 1;" ::: "memory")
#define CP_WAIT0()  asm volatile("cp.async.wait_group 0;" ::: "memory")
#define SWZ64A(o) ((o) ^ (((o) >> 2) & 0x70))
#define SWZ128(o) ((o) ^ (((o) >> 3) & 0x70))
#define SWZ256(o) ((o) ^ (((o) >> 4) & 0x70))

// ============ problem constants ============
#define FIN  1024
#define SEQ  128
#define CH   32
#define NC   32

// ============ pre-split global staging (fp16) ============
__device__ __align__(16) __half g_WqH[1024 * 1024];
__device__ __align__(16) __half g_WqL[1024 * 1024];
__device__ __align__(16) __half g_WkH[1024 * 1024];
__device__ __align__(16) __half g_WkL[1024 * 1024];
__device__ __align__(16) __half g_x[256 * 1024 * 128];

__global__ void __launch_bounds__(256) prep_w_kernel(const float* __restrict__ Wq,
                                                     const float* __restrict__ Wk) {
    int i = blockIdx.x * 256 + threadIdx.x;
    float4 v = ((const float4*)Wq)[i];
    uint2 h, l;
    split4h(v, h, l);
    ((uint2*)g_WqH)[i] = h; ((uint2*)g_WqL)[i] = l;
    v = ((const float4*)Wk)[i];
    split4h(v, h, l);
    ((uint2*)g_WkH)[i] = h; ((uint2*)g_WkL)[i] = l;
}
__global__ void __launch_bounds__(256) prep_x_kernel(const float* __restrict__ x) {
    size_t i = (size_t)blockIdx.x * 256 + threadIdx.x;
    ((uint2*)g_x)[i] = cvt4h(((const float4*)x)[i]);
}

// ============ SMEM layout (bytes) ============
#define BUF_SZ  40960
#define BW_H    0
#define BW_L    16384
#define BX_S    32768
#define KT_L    0
#define QT_H    81920
#define QT_L    114688
#define KT_H    147456
#define W_SM    180224
#define BQ_SM   181248
#define BK_SM   181760
#define WO_SM   182272
#define SMEM_TOTAL 182784

__global__ void __launch_bounds__(256, 1)
Attention_75402445849133_kernel(const float* __restrict__ x,
                                const float* __restrict__ bq, const float* __restrict__ bk,
                                const float* __restrict__ Wo, const float* __restrict__ bo,
                                float* __restrict__ out)
{
    extern __shared__ char smem[];
    const uint32_t sbase = smem_u32(smem);
    const int tid = threadIdx.x;
    const int w   = tid >> 5;
    const int lid = tid & 31;
    const int gq  = lid >> 2;
    const int tq  = lid & 3;
    const int g   = blockIdx.x;
    const int b   = blockIdx.y;

    float* wsm = (float*)(smem + W_SM);
    float* bqs = (float*)(smem + BQ_SM);
    float* bks = (float*)(smem + BK_SM);
    float* wos = (float*)(smem + WO_SM);
    if (tid < 128) {
        bqs[tid] = bq[g * 128 + tid];
        bks[tid] = bk[g * 128 + tid];
        wos[tid] = Wo[tid];
    }
    wsm[tid] = 0.0f;

    const float* xb = x + (size_t)b * FIN * SEQ;
    const __half* xbh = g_x + (size_t)b * FIN * SEQ;

    const int m0 = (w & 3) * 64;
    const int n0 = (w >> 2) * 64;

    // ---- cp.async coordinates ----
    const __half* wbH[4];
    const __half* wbL[4];
    uint32_t wsoff[4];
    #pragma unroll
    for (int j = 0; j < 4; j++) {
        int wi = j * 256 + tid;
        int row = wi >> 2, cg = wi & 3;
        wsoff[j] = SWZ64A((uint32_t)(row * 64 + cg * 16));
        int isq = (row < 128);
        int rl  = row & 127;
        wbH[j] = (isq ? g_WqH : g_WkH) + (size_t)(g * 128 + rl) * FIN + cg * 8;
        wbL[j] = (isq ? g_WqL : g_WkL) + (size_t)(g * 128 + rl) * FIN + cg * 8;
    }
    uint32_t xsoff[2];
    int xrr[2], xsg[2];
    #pragma unroll
    for (int j = 0; j < 2; j++) {
        int xi = j * 256 + tid;
        xrr[j] = xi >> 4; xsg[j] = xi & 15;
        xsoff[j] = SWZ256((uint32_t)(xrr[j] * 256 + xsg[j] * 16));
    }

    float creg[4][8][4];
    #pragma unroll
    for (int a = 0; a < 4; a++)
        #pragma unroll
        for (int n = 0; n < 8; n++)
            #pragma unroll
            for (int j = 0; j < 4; j++) creg[a][n][j] = 0.f;

    // prologue: issue chunk 0
    #pragma unroll
    for (int j = 0; j < 4; j++) {
        cpa16(sbase + BW_H + wsoff[j], wbH[j]);
        cpa16(sbase + BW_L + wsoff[j], wbL[j]);
    }
    #pragma unroll
    for (int j = 0; j < 2; j++)
        cpa16(sbase + BX_S + xsoff[j], xbh + xrr[j] * SEQ + xsg[j] * 8);
    CP_COMMIT();

    // ================= fused Q+K projection mainloop (2 MMA terms) =============
    #pragma unroll 1
    for (int kc = 0; kc < NC; kc++) {
        if (kc + 1 < NC) {
            const uint32_t nb = sbase + ((kc + 1) & 1) * BUF_SZ;
            const int kn = (kc + 1) * CH;
            #pragma unroll
            for (int j = 0; j < 4; j++) {
                cpa16(nb + BW_H + wsoff[j], wbH[j] + kn);
                cpa16(nb + BW_L + wsoff[j], wbL[j] + kn);
            }
            #pragma unroll
            for (int j = 0; j < 2; j++)
                cpa16(nb + BX_S + xsoff[j], xbh + (size_t)(kn + xrr[j]) * SEQ + xsg[j] * 8);
            CP_COMMIT();
            CP_WAIT1();
        } else {
            CP_WAIT0();
        }
        __syncthreads();

        const uint32_t bufb = sbase + (kc & 1) * BUF_SZ;
        #pragma unroll
        for (int ks = 0; ks < 2; ks++) {
            const int k0 = ks * 16;
            uint32_t aH[4][4], aL[4][4];
            #pragma unroll
            for (int mt = 0; mt < 4; mt++) {
                int row = m0 + mt * 16 + (lid & 15);
                int col = k0 + ((lid >> 4) << 3);
                uint32_t off = SWZ64A((uint32_t)(row * 64 + col * 2));
                ldsm4(aH[mt], bufb + BW_H + off);
                ldsm4(aL[mt], bufb + BW_L + off);
            }
            // B fragment software pipeline: prefetch np+1 while issuing MMAs on np
            const int tL  = lid >> 3;
            const int krw = k0 + ((tL & 1) << 3) + (lid & 7);
            uint32_t bCur[4], bNxt[4];
            {
                int nc = n0 + ((tL >> 1) << 3);
                ldsm4t(bCur, bufb + BX_S + SWZ256((uint32_t)(krw * 256 + nc * 2)));
            }
            #pragma unroll
            for (int np = 0; np < 4; np++) {
                if (np < 3) {
                    int nc = n0 + (np + 1) * 16 + ((tL >> 1) << 3);
                    ldsm4t(bNxt, bufb + BX_S + SWZ256((uint32_t)(krw * 256 + nc * 2)));
                }
                // term-major, mt-inner: >=4 independent MMAs between accumulator reuse
                #pragma unroll
                for (int mt = 0; mt < 4; mt++) mma16816(creg[mt][np * 2],     aH[mt], bCur[0], bCur[1]);
                #pragma unroll
                for (int mt = 0; mt < 4; mt++) mma16816(creg[mt][np * 2 + 1], aH[mt], bCur[2], bCur[3]);
                #pragma unroll
                for (int mt = 0; mt < 4; mt++) mma16816(creg[mt][np * 2],     aL[mt], bCur[0], bCur[1]);
                #pragma unroll
                for (int mt = 0; mt < 4; mt++) mma16816(creg[mt][np * 2 + 1], aL[mt], bCur[2], bCur[3]);
                #pragma unroll
                for (int j = 0; j < 4; j++) bCur[j] = bNxt[j];
            }
        }
        __syncthreads();
    }

    // ---- writeback: stacked C -> qT / kT split fp16 (+bias; q scaled 1/8) ----
    {
        #pragma unroll
        for (int mt = 0; mt < 4; mt++)
            #pragma unroll
            for (int rj = 0; rj < 2; rj++) {
                int m = m0 + mt * 16 + rj * 8 + gq;
                int isq = (m < 128);
                int mloc = m & 127;
                float bias = isq ? bqs[mloc] : bks[mloc];
                int head = mloc >> 6, d = mloc & 63;
                char* dh = smem + (isq ? QT_H : KT_H) + head * 16384;
                char* dl = smem + (isq ? QT_L : KT_L) + head * 16384;
                #pragma unroll
                for (int nt = 0; nt < 8; nt++)
                    #pragma unroll
                    for (int jj = 0; jj < 2; jj++) {
                        int n = n0 + nt * 8 + tq * 2 + jj;
                        float v = creg[mt][nt][rj * 2 + jj] + bias;
                        if (isq) v *= 0.125f;
                        __half h = __float2half_rn(v);
                        __half l = __float2half_rn(v - __half2float(h));
                        uint32_t off = SWZ128((uint32_t)(n * 128 + d * 2));
                        *(__half*)(dh + off) = h;
                        *(__half*)(dl + off) = l;
                    }
            }
    }
    __syncthreads();

    // ================= Phase 2: scores (3-term fp16) + softmax + w reduction ====
    {
        const int head = w >> 2;
        const int sb0  = (w & 3) * 32;
        const uint32_t qh = sbase + QT_H + head * 16384;
        const uint32_t ql = sbase + QT_L + head * 16384;
        const uint32_t kh = sbase + KT_H + head * 16384;
        const uint32_t kl = sbase + KT_L + head * 16384;

        float wacc[16][2];
        #pragma unroll
        for (int nt = 0; nt < 16; nt++) { wacc[nt][0] = 0.f; wacc[nt][1] = 0.f; }

        #pragma unroll 1
        for (int chunk = 0; chunk < 2; chunk++) {
            const int s0 = sb0 + chunk * 16;
            float sc[16][4];
            #pragma unroll
            for (int nt = 0; nt < 16; nt++)
                #pragma unroll
                for (int j = 0; j < 4; j++) sc[nt][j] = 0.f;

            #pragma unroll
            for (int ks = 0; ks < 4; ks++) {
                const int k0 = ks * 16;
                uint32_t aH[4], aL[4];
                {
                    int row = s0 + (lid & 15);
                    int col = k0 + ((lid >> 4) << 3);
                    uint32_t off = SWZ128((uint32_t)(row * 128 + col * 2));
                    ldsm4(aH, qh + off);
                    ldsm4(aL, ql + off);
                }
                #pragma unroll
                for (int npp = 0; npp < 4; npp++) {
                    // process two adjacent np tiles to interleave accumulators
                    int tL = lid >> 3;
                    int ccol = k0 + ((tL & 1) << 3);
                    int r0 = (npp * 2) * 16 + ((tL >> 1) << 3) + (lid & 7);
                    int r1 = (npp * 2 + 1) * 16 + ((tL >> 1) << 3) + (lid & 7);
                    uint32_t bH0[4], bL0[4], bH1[4], bL1[4];
                    ldsm4(bH0, kh + SWZ128((uint32_t)(r0 * 128 + ccol * 2)));
                    ldsm4(bL0, kl + SWZ128((uint32_t)(r0 * 128 + ccol * 2)));
                    ldsm4(bH1, kh + SWZ128((uint32_t)(r1 * 128 + ccol * 2)));
                    ldsm4(bL1, kl + SWZ128((uint32_t)(r1 * 128 + ccol * 2)));
                    float* s00 = sc[npp * 4 + 0];
                    float* s01 = sc[npp * 4 + 1];
                    float* s10 = sc[npp * 4 + 2];
                    float* s11 = sc[npp * 4 + 3];
                    mma16816(s00, aH, bH0[0], bH0[1]);
                    mma16816(s01, aH, bH0[2], bH0[3]);
                    mma16816(s10, aH, bH1[0], bH1[1]);
                    mma16816(s11, aH, bH1[2], bH1[3]);
                    mma16816(s00, aH, bL0[0], bL0[1]);
                    mma16816(s01, aH, bL0[2], bL0[3]);
                    mma16816(s10, aH, bL1[0], bL1[1]);
                    mma16816(s11, aH, bL1[2], bL1[3]);
                    mma16816(s00, aL, bH0[0], bH0[1]);
                    mma16816(s01, aL, bH0[2], bH0[3]);
                    mma16816(s10, aL, bH1[0], bH1[1]);
                    mma16816(s11, aL, bH1[2], bH1[3]);
                }
            }
            float mx0 = -1e30f, mx1 = -1e30f;
            #pragma unroll
            for (int nt = 0; nt < 16; nt++) {
                mx0 = fmaxf(mx0, fmaxf(sc[nt][0], sc[nt][1]));
                mx1 = fmaxf(mx1, fmaxf(sc[nt][2], sc[nt][3]));
            }
            mx0 = fmaxf(mx0, __shfl_xor_sync(0xffffffffu, mx0, 1));
            mx0 = fmaxf(mx0, __shfl_xor_sync(0xffffffffu, mx0, 2));
            mx1 = fmaxf(mx1, __shfl_xor_sync(0xffffffffu, mx1, 1));
            mx1 = fmaxf(mx1, __shfl_xor_sync(0xffffffffu, mx1, 2));
            float Z0 = 0.f, Z1 = 0.f;
            #pragma unroll
            for (int nt = 0; nt < 16; nt++) {
                sc[nt][0] = __expf(sc[nt][0] - mx0); Z0 += sc[nt][0];
                sc[nt][1] = __expf(sc[nt][1] - mx0); Z0 += sc[nt][1];
                sc[nt][2] = __expf(sc[nt][2] - mx1); Z1 += sc[nt][2];
                sc[nt][3] = __expf(sc[nt][3] - mx1); Z1 += sc[nt][3];
            }
            Z0 += __shfl_xor_sync(0xffffffffu, Z0, 1);
            Z0 += __shfl_xor_sync(0xffffffffu, Z0, 2);
            Z1 += __shfl_xor_sync(0xffffffffu, Z1, 1);
            Z1 += __shfl_xor_sync(0xffffffffu, Z1, 2);
            const float c0 = wos[s0 + gq]     / Z0;
            const float c1 = wos[s0 + 8 + gq] / Z1;
            #pragma unroll
            for (int nt = 0; nt < 16; nt++) {
                wacc[nt][0] += sc[nt][0] * c0 + sc[nt][2] * c1;
                wacc[nt][1] += sc[nt][1] * c0 + sc[nt][3] * c1;
            }
        }
        #pragma unroll
        for (int d = 4; d < 32; d <<= 1)
            #pragma unroll
            for (int nt = 0; nt < 16; nt++) {
                wacc[nt][0] += __shfl_xor_sync(0xffffffffu, wacc[nt][0], d);
                wacc[nt][1] += __shfl_xor_sync(0xffffffffu, wacc[nt][1], d);
            }
        if (lid < 4) {
            #pragma unroll
            for (int nt = 0; nt < 16; nt++) {
                atomicAdd(&wsm[head * 128 + nt * 8 + 2 * lid],     wacc[nt][0]);
                atomicAdd(&wsm[head * 128 + nt * 8 + 2 * lid + 1], wacc[nt][1]);
            }
        }
    }
    __syncthreads();

    // ================= Phase 3: out[b, g*128+f] = sum_t w[head][t]*x[b,f,t] + bo
    if (tid < 128) {
        const float* wv2 = wsm + (tid >> 6) * 128;
        const float4* x4 = (const float4*)(xb + (size_t)(g * 128 + tid) * SEQ);
        float acc = 0.f;
        #pragma unroll 8
        for (int t4 = 0; t4 < 32; t4++) {
            float4 xvv = x4[t4];
            acc += xvv.x * wv2[t4 * 4 + 0] + xvv.y * wv2[t4 * 4 + 1]
                 + xvv.z * wv2[t4 * 4 + 2] + xvv.w * wv2[t4 * 4 + 3];
        }
        out[(size_t)b * FIN + g * 128 + tid] = acc + bo[0];
    }
}

extern "C" void kernel_launch(void* const* d_in, const int* in_sizes, int n_in,
                              void* d_out, int out_size)
{
    (void)in_sizes; (void)n_in; (void)out_size;
    const float* x  = (const float*)d_in[0];
    const float* Wq = (const float*)d_in[1];
    const float* bq = (const float*)d_in[2];
    const float* Wk = (const float*)d_in[3];
    const float* bk = (const float*)d_in[4];
    const float* Wo = (const float*)d_in[5];
    const float* bo = (const float*)d_in[6];
    float* out = (float*)d_out;

    prep_w_kernel<<<1024, 256>>>(Wq, Wk);
    prep_x_kernel<<<32768, 256>>>(x);

    cudaFuncSetAttribute(Attention_75402445849133_kernel,
                         cudaFuncAttributeMaxDynamicSharedMemorySize, SMEM_TOTAL);
    dim3 grid(8, 256, 1);
    Attention_75402445849133_kernel<<<grid, 256, SMEM_TOTAL>>>(x, bq, bk, Wo, bo, out);
}